// round 1
// baseline (speedup 1.0000x reference)
#include <cuda_runtime.h>
#include <cuda_bf16.h>
#include <math.h>

// Problem constants (fixed by the reference)
#define NNODES 50000
#define NEDGES 1600000
#define NFEAT  512
#define NHID   256
#define NCLASS 40

// Scratch (allocation-free rule: __device__ globals)
__device__ float g_bufA[NNODES * NHID];   // 51.2 MB
__device__ float g_bufB[NNODES * NHID];   // 51.2 MB
__device__ int   g_rowptr[NNODES + 1];

// ---------------------------------------------------------------------------
// row_ptr build: edge_rows is sorted -> lower_bound per row
// ---------------------------------------------------------------------------
__global__ void build_rowptr_kernel(const int* __restrict__ rows, int E, int* __restrict__ rp) {
    int r = blockIdx.x * blockDim.x + threadIdx.x;
    if (r > NNODES) return;
    int lo = 0, hi = E;
    while (lo < hi) {
        int mid = (lo + hi) >> 1;
        if (__ldg(&rows[mid]) < r) lo = mid + 1; else hi = mid;
    }
    rp[r] = lo;
}

// ---------------------------------------------------------------------------
// SGEMM + bias: C[M,N] = A[M,K] @ B[K,N] + bias[N]
// BM=128, BN=128, BK=8, 256 threads, 8x8 per thread
// ---------------------------------------------------------------------------
#define BM 128
#define BN 128
#define BK 8

__global__ __launch_bounds__(256, 2)
void sgemm_bias_kernel(const float* __restrict__ A, const float* __restrict__ B,
                       const float* __restrict__ bias, float* __restrict__ C,
                       int M, int N, int K) {
    __shared__ float As[BK][BM + 4];
    __shared__ float Bs[BK][BN];

    const int tid = threadIdx.x;
    const int blockRow = blockIdx.y * BM;
    const int blockCol = blockIdx.x * BN;
    const int ty = tid >> 4;          // 0..15
    const int tx = tid & 15;          // 0..15

    // A tile load mapping: 128 rows x 8 k; thread loads float4
    const int arow = tid >> 1;            // 0..127
    const int akcol = (tid & 1) * 4;      // 0 or 4
    // B tile load mapping: 8 k x 128 cols; thread loads float4
    const int brow = tid >> 5;            // 0..7
    const int bcol = (tid & 31) * 4;      // 0..124

    float acc[8][8];
#pragma unroll
    for (int i = 0; i < 8; i++)
#pragma unroll
        for (int j = 0; j < 8; j++) acc[i][j] = 0.f;

    const int gr_a = blockRow + arow;
    const bool a_ok = (gr_a < M);

    for (int k0 = 0; k0 < K; k0 += BK) {
        float4 a4 = make_float4(0.f, 0.f, 0.f, 0.f);
        if (a_ok) a4 = *(const float4*)&A[(long)gr_a * K + k0 + akcol];
        As[akcol + 0][arow] = a4.x;
        As[akcol + 1][arow] = a4.y;
        As[akcol + 2][arow] = a4.z;
        As[akcol + 3][arow] = a4.w;

        float4 b4 = *(const float4*)&B[(long)(k0 + brow) * N + blockCol + bcol];
        *(float4*)&Bs[brow][bcol] = b4;

        __syncthreads();

#pragma unroll
        for (int kk = 0; kk < BK; kk++) {
            float a[8], b[8];
#pragma unroll
            for (int i = 0; i < 8; i++) a[i] = As[kk][ty * 8 + i];
#pragma unroll
            for (int j = 0; j < 8; j++) b[j] = Bs[kk][tx * 8 + j];
#pragma unroll
            for (int i = 0; i < 8; i++)
#pragma unroll
                for (int j = 0; j < 8; j++) acc[i][j] = fmaf(a[i], b[j], acc[i][j]);
        }
        __syncthreads();
    }

    // epilogue: + bias, store
#pragma unroll
    for (int i = 0; i < 8; i++) {
        int gr = blockRow + ty * 8 + i;
        if (gr >= M) continue;
#pragma unroll
        for (int j = 0; j < 8; j += 4) {
            int gc = blockCol + tx * 8 + j;
            float4 v;
            v.x = acc[i][j + 0] + __ldg(&bias[gc + 0]);
            v.y = acc[i][j + 1] + __ldg(&bias[gc + 1]);
            v.z = acc[i][j + 2] + __ldg(&bias[gc + 2]);
            v.w = acc[i][j + 3] + __ldg(&bias[gc + 3]);
            *(float4*)&C[(long)gr * N + gc] = v;
        }
    }
}

// ---------------------------------------------------------------------------
// SpMM + ReLU: H[r,f] = relu( sum_{e in row r} val[e] * S[col[e], f] )
// one block (256 threads) per row, thread-per-feature, edges staged in smem
// ---------------------------------------------------------------------------
__global__ __launch_bounds__(256)
void spmm_relu_kernel(const int* __restrict__ rp, const int* __restrict__ cols,
                      const float* __restrict__ vals, const float* __restrict__ S,
                      float* __restrict__ H) {
    __shared__ int   sc[256];
    __shared__ float sv[256];

    const int r = blockIdx.x;
    const int f = threadIdx.x;
    const int start = rp[r];
    const int end = rp[r + 1];

    float acc = 0.f;
    for (int base = start; base < end; base += 256) {
        int n = min(256, end - base);
        __syncthreads();
        if (f < n) {
            sc[f] = __ldg(&cols[base + f]);
            sv[f] = __ldg(&vals[base + f]);
        }
        __syncthreads();
        int i = 0;
        // unrolled by 4 for MLP
        for (; i + 4 <= n; i += 4) {
            int c0 = sc[i + 0], c1 = sc[i + 1], c2 = sc[i + 2], c3 = sc[i + 3];
            float v0 = sv[i + 0], v1 = sv[i + 1], v2 = sv[i + 2], v3 = sv[i + 3];
            float s0 = __ldg(&S[(long)c0 * NHID + f]);
            float s1 = __ldg(&S[(long)c1 * NHID + f]);
            float s2 = __ldg(&S[(long)c2 * NHID + f]);
            float s3 = __ldg(&S[(long)c3 * NHID + f]);
            acc = fmaf(v0, s0, acc);
            acc = fmaf(v1, s1, acc);
            acc = fmaf(v2, s2, acc);
            acc = fmaf(v3, s3, acc);
        }
        for (; i < n; i++) {
            acc = fmaf(sv[i], __ldg(&S[(long)sc[i] * NHID + f]), acc);
        }
    }
    H[(long)r * NHID + f] = fmaxf(acc, 0.f);
}

// ---------------------------------------------------------------------------
// Fused FC + log_softmax: out[n,c] = logsoftmax(Z[n,:] @ Wfc + bfc)[c]
// 256 threads/block, 64 nodes/block, 4 threads per node (10 classes each)
// ---------------------------------------------------------------------------
__global__ __launch_bounds__(256)
void fc_logsoftmax_kernel(const float* __restrict__ Z, const float* __restrict__ W,
                          const float* __restrict__ bias, float* __restrict__ out, int M) {
    __shared__ float Ws[NHID * NCLASS];   // 40 KB
    __shared__ float bs[NCLASS];

    const int tid = threadIdx.x;
    for (int i = tid; i < NHID * NCLASS; i += 256) Ws[i] = __ldg(&W[i]);
    if (tid < NCLASS) bs[tid] = __ldg(&bias[tid]);
    __syncthreads();

    const int n_raw = blockIdx.x * 64 + (tid >> 2);
    const bool valid = (n_raw < M);
    const int n = valid ? n_raw : (M - 1);   // clamp: keep all lanes alive for shfl
    const int q = tid & 3;                   // class group: classes q*10 .. q*10+9

    float acc[10];
#pragma unroll
    for (int c = 0; c < 10; c++) acc[c] = bs[q * 10 + c];

    const float* zrow = Z + (long)n * NHID;
#pragma unroll 4
    for (int k = 0; k < NHID; k++) {
        float zv = __ldg(&zrow[k]);
        const float* wrow = &Ws[k * NCLASS + q * 10];
#pragma unroll
        for (int c = 0; c < 10; c++) acc[c] = fmaf(zv, wrow[c], acc[c]);
    }

    // log_softmax across the 40 classes held by the 4-lane group
    float m = acc[0];
#pragma unroll
    for (int c = 1; c < 10; c++) m = fmaxf(m, acc[c]);
    m = fmaxf(m, __shfl_xor_sync(0xffffffffu, m, 1));
    m = fmaxf(m, __shfl_xor_sync(0xffffffffu, m, 2));

    float s = 0.f;
#pragma unroll
    for (int c = 0; c < 10; c++) s += expf(acc[c] - m);
    s += __shfl_xor_sync(0xffffffffu, s, 1);
    s += __shfl_xor_sync(0xffffffffu, s, 2);

    const float lse = m + logf(s);
    if (valid) {
#pragma unroll
        for (int c = 0; c < 10; c++)
            out[(long)n * NCLASS + q * 10 + c] = acc[c] - lse;
    }
}

// ---------------------------------------------------------------------------
// launch
// ---------------------------------------------------------------------------
extern "C" void kernel_launch(void* const* d_in, const int* in_sizes, int n_in,
                              void* d_out, int out_size) {
    const float* x         = (const float*)d_in[0];
    const int*   edge_rows = (const int*)  d_in[1];
    const int*   edge_cols = (const int*)  d_in[2];
    const float* edge_vals = (const float*)d_in[3];
    const float* W1        = (const float*)d_in[4];
    const float* b1        = (const float*)d_in[5];
    const float* W2        = (const float*)d_in[6];
    const float* b2        = (const float*)d_in[7];
    const float* Wfc       = (const float*)d_in[8];
    const float* bfc       = (const float*)d_in[9];
    float* out = (float*)d_out;

    float* bufA;
    float* bufB;
    int*   rowptr;
    cudaGetSymbolAddress((void**)&bufA, g_bufA);
    cudaGetSymbolAddress((void**)&bufB, g_bufB);
    cudaGetSymbolAddress((void**)&rowptr, g_rowptr);

    // 1. CSR row pointers from sorted edge_rows
    build_rowptr_kernel<<<(NNODES + 1 + 255) / 256, 256>>>(edge_rows, NEDGES, rowptr);

    // 2. support1 = x @ W1 + b1   [N, 256]
    {
        dim3 grid(NHID / BN, (NNODES + BM - 1) / BM);
        sgemm_bias_kernel<<<grid, 256>>>(x, W1, b1, bufA, NNODES, NHID, NFEAT);
    }
    // 3. h1 = relu(A @ support1)
    spmm_relu_kernel<<<NNODES, 256>>>(rowptr, edge_cols, edge_vals, bufA, bufB);

    // 4. support2 = h1 @ W2 + b2
    {
        dim3 grid(NHID / BN, (NNODES + BM - 1) / BM);
        sgemm_bias_kernel<<<grid, 256>>>(bufB, W2, b2, bufA, NNODES, NHID, NHID);
    }
    // 5. z = relu(A @ support2)
    spmm_relu_kernel<<<NNODES, 256>>>(rowptr, edge_cols, edge_vals, bufA, bufB);

    // 6. out = log_softmax(z @ Wfc + bfc)
    fc_logsoftmax_kernel<<<(NNODES + 63) / 64, 256>>>(bufB, Wfc, bfc, out, NNODES);
}

// round 2
// speedup vs baseline: 1.5590x; 1.5590x over previous
#include <cuda_runtime.h>
#include <cuda_bf16.h>
#include <math.h>
#include <stdint.h>

// Problem constants (fixed by the reference)
#define NNODES 50000
#define NEDGES 1600000
#define NFEAT  512
#define NHID   256
#define NCLASS 40

// Scratch (allocation-free rule: __device__ globals)
__device__ float g_bufA[NNODES * NHID];   // 51.2 MB
__device__ float g_bufB[NNODES * NHID];   // 51.2 MB
__device__ int   g_rowptr[NNODES + 1];

__device__ __forceinline__ uint32_t f2tf(float x) {
    uint32_t u;
    asm("cvt.rna.tf32.f32 %0, %1;" : "=r"(u) : "f"(x));
    return u;
}

// ---------------------------------------------------------------------------
// row_ptr build: edge_rows is sorted -> lower_bound per row
// ---------------------------------------------------------------------------
__global__ void build_rowptr_kernel(const int* __restrict__ rows, int E, int* __restrict__ rp) {
    int r = blockIdx.x * blockDim.x + threadIdx.x;
    if (r > NNODES) return;
    int lo = 0, hi = E;
    while (lo < hi) {
        int mid = (lo + hi) >> 1;
        if (__ldg(&rows[mid]) < r) lo = mid + 1; else hi = mid;
    }
    rp[r] = lo;
}

// ---------------------------------------------------------------------------
// TF32 tensor-core GEMM + bias: C[M,N] = A[M,K] @ B[K,N] + bias[N]
// Block tile 128x128, K-chunk 32. 8 warps as 2(m) x 4(n), warp tile 64x32.
// mma.sync.aligned.m16n8k8.row.col.f32.tf32.tf32.f32
// ---------------------------------------------------------------------------
#define TBM 128
#define TBN 128
#define TBK 32
#define AS_STRIDE (TBM + 4)   // As[k][m], padded
#define BS_STRIDE (TBN + 4)   // Bs[k][n], padded

__global__ __launch_bounds__(256, 1)
void gemm_tf32_bias(const float* __restrict__ A, const float* __restrict__ B,
                    const float* __restrict__ bias, float* __restrict__ C,
                    int M, int N, int K) {
    __shared__ uint32_t As[TBK * AS_STRIDE];
    __shared__ uint32_t Bs[TBK * BS_STRIDE];

    const int tid  = threadIdx.x;
    const int warp = tid >> 5;
    const int lane = tid & 31;
    const int g = lane >> 2;        // 0..7
    const int t = lane & 3;         // 0..3
    const int wm = warp & 1;        // 0..1 -> 64-row slab
    const int wn = warp >> 1;       // 0..3 -> 32-col slab

    const int blockRow = blockIdx.y * TBM;
    const int blockCol = blockIdx.x * TBN;

    // A tile load mapping: 128 rows x 32 k; 2 threads/row, 4 float4 each
    const int a_m   = tid >> 1;        // 0..127
    const int a_p   = tid & 1;         // parity: float4 quads p+2j
    const int a_row = blockRow + a_m;
    const bool a_ok = (a_row < M);

    // B tile load mapping: 32 k x 128 n; 8 threads/k-row, 4 float4 each
    const int b_k  = tid >> 3;         // 0..31
    const int b_nq = tid & 7;          // float4 quads nq+8j

    const int ntiles = K / TBK;

    float4 pa[4], pb[4];
    // prefetch tile 0
    {
#pragma unroll
        for (int j = 0; j < 4; j++) {
            int kk = 4 * (a_p + 2 * j);
            pa[j] = a_ok ? *(const float4*)&A[(size_t)a_row * K + kk]
                         : make_float4(0.f, 0.f, 0.f, 0.f);
        }
#pragma unroll
        for (int j = 0; j < 4; j++) {
            int nn = 4 * (b_nq + 8 * j);
            pb[j] = *(const float4*)&B[(size_t)b_k * N + blockCol + nn];
        }
    }

    float c[4][4][4];
#pragma unroll
    for (int mt = 0; mt < 4; mt++)
#pragma unroll
        for (int nt = 0; nt < 4; nt++)
#pragma unroll
            for (int q = 0; q < 4; q++) c[mt][nt][q] = 0.f;

    for (int kt = 0; kt < ntiles; kt++) {
        // commit prefetched tile to smem (tf32-rounded)
#pragma unroll
        for (int j = 0; j < 4; j++) {
            int kk = 4 * (a_p + 2 * j);
            As[(kk + 0) * AS_STRIDE + a_m] = f2tf(pa[j].x);
            As[(kk + 1) * AS_STRIDE + a_m] = f2tf(pa[j].y);
            As[(kk + 2) * AS_STRIDE + a_m] = f2tf(pa[j].z);
            As[(kk + 3) * AS_STRIDE + a_m] = f2tf(pa[j].w);
        }
#pragma unroll
        for (int j = 0; j < 4; j++) {
            int nn = 4 * (b_nq + 8 * j);
            Bs[b_k * BS_STRIDE + nn + 0] = f2tf(pb[j].x);
            Bs[b_k * BS_STRIDE + nn + 1] = f2tf(pb[j].y);
            Bs[b_k * BS_STRIDE + nn + 2] = f2tf(pb[j].z);
            Bs[b_k * BS_STRIDE + nn + 3] = f2tf(pb[j].w);
        }
        __syncthreads();

        // issue next tile's global loads (overlap with compute)
        if (kt + 1 < ntiles) {
            int k0 = (kt + 1) * TBK;
#pragma unroll
            for (int j = 0; j < 4; j++) {
                int kk = 4 * (a_p + 2 * j);
                pa[j] = a_ok ? *(const float4*)&A[(size_t)a_row * K + k0 + kk]
                             : make_float4(0.f, 0.f, 0.f, 0.f);
            }
#pragma unroll
            for (int j = 0; j < 4; j++) {
                int nn = 4 * (b_nq + 8 * j);
                pb[j] = *(const float4*)&B[(size_t)(k0 + b_k) * N + blockCol + nn];
            }
        }

        // compute 4 k-steps of 8
#pragma unroll
        for (int ks = 0; ks < 4; ks++) {
            const int k0 = ks * 8;
            uint32_t af[4][4];
            uint32_t bf[4][2];
#pragma unroll
            for (int mt = 0; mt < 4; mt++) {
                int m0 = wm * 64 + mt * 16;
                af[mt][0] = As[(k0 + t) * AS_STRIDE + m0 + g];
                af[mt][1] = As[(k0 + t) * AS_STRIDE + m0 + 8 + g];
                af[mt][2] = As[(k0 + t + 4) * AS_STRIDE + m0 + g];
                af[mt][3] = As[(k0 + t + 4) * AS_STRIDE + m0 + 8 + g];
            }
#pragma unroll
            for (int nt = 0; nt < 4; nt++) {
                int n0 = wn * 32 + nt * 8;
                bf[nt][0] = Bs[(k0 + t) * BS_STRIDE + n0 + g];
                bf[nt][1] = Bs[(k0 + t + 4) * BS_STRIDE + n0 + g];
            }
#pragma unroll
            for (int mt = 0; mt < 4; mt++)
#pragma unroll
                for (int nt = 0; nt < 4; nt++) {
                    asm volatile(
                        "mma.sync.aligned.m16n8k8.row.col.f32.tf32.tf32.f32 "
                        "{%0,%1,%2,%3}, {%4,%5,%6,%7}, {%8,%9}, {%0,%1,%2,%3};\n"
                        : "+f"(c[mt][nt][0]), "+f"(c[mt][nt][1]),
                          "+f"(c[mt][nt][2]), "+f"(c[mt][nt][3])
                        : "r"(af[mt][0]), "r"(af[mt][1]), "r"(af[mt][2]), "r"(af[mt][3]),
                          "r"(bf[nt][0]), "r"(bf[nt][1]));
                }
        }
        __syncthreads();
    }

    // epilogue: + bias, guarded store
#pragma unroll
    for (int mt = 0; mt < 4; mt++) {
        int r0 = blockRow + wm * 64 + mt * 16 + g;
        int r1 = r0 + 8;
#pragma unroll
        for (int nt = 0; nt < 4; nt++) {
            int col = blockCol + wn * 32 + nt * 8 + 2 * t;
            float bx = __ldg(&bias[col]);
            float by = __ldg(&bias[col + 1]);
            if (r0 < M) {
                float2 v = make_float2(c[mt][nt][0] + bx, c[mt][nt][1] + by);
                *(float2*)&C[(size_t)r0 * N + col] = v;
            }
            if (r1 < M) {
                float2 v = make_float2(c[mt][nt][2] + bx, c[mt][nt][3] + by);
                *(float2*)&C[(size_t)r1 * N + col] = v;
            }
        }
    }
}

// ---------------------------------------------------------------------------
// SpMM + ReLU: H[r,f] = relu( sum_{e in row r} val[e] * S[col[e], f] )
// one warp per row; lane stages one edge; shfl-broadcast; 8 feats/lane (2x float4)
// ---------------------------------------------------------------------------
__global__ __launch_bounds__(256)
void spmm_relu_warp(const int* __restrict__ rp, const int* __restrict__ cols,
                    const float* __restrict__ vals, const float* __restrict__ S,
                    float* __restrict__ H) {
    const int warp = threadIdx.x >> 5;
    const int lane = threadIdx.x & 31;
    const int r = blockIdx.x * 8 + warp;
    if (r >= NNODES) return;

    const int start = rp[r];
    const int end   = rp[r + 1];
    const int foff  = lane * 8;

    float4 acc0 = make_float4(0.f, 0.f, 0.f, 0.f);
    float4 acc1 = make_float4(0.f, 0.f, 0.f, 0.f);

    for (int base = start; base < end; base += 32) {
        int idx = base + lane;
        int   cc = 0;
        float vv = 0.f;
        if (idx < end) {
            cc = __ldg(&cols[idx]);
            vv = __ldg(&vals[idx]);
        }
        const int n = min(32, end - base);
#pragma unroll 4
        for (int j = 0; j < n; j++) {
            int   c = __shfl_sync(0xffffffffu, cc, j);
            float v = __shfl_sync(0xffffffffu, vv, j);
            const float4* p = (const float4*)(S + (size_t)c * NHID + foff);
            float4 s0 = __ldg(p);
            float4 s1 = __ldg(p + 1);
            acc0.x = fmaf(v, s0.x, acc0.x);
            acc0.y = fmaf(v, s0.y, acc0.y);
            acc0.z = fmaf(v, s0.z, acc0.z);
            acc0.w = fmaf(v, s0.w, acc0.w);
            acc1.x = fmaf(v, s1.x, acc1.x);
            acc1.y = fmaf(v, s1.y, acc1.y);
            acc1.z = fmaf(v, s1.z, acc1.z);
            acc1.w = fmaf(v, s1.w, acc1.w);
        }
    }

    float4 o0 = make_float4(fmaxf(acc0.x, 0.f), fmaxf(acc0.y, 0.f),
                            fmaxf(acc0.z, 0.f), fmaxf(acc0.w, 0.f));
    float4 o1 = make_float4(fmaxf(acc1.x, 0.f), fmaxf(acc1.y, 0.f),
                            fmaxf(acc1.z, 0.f), fmaxf(acc1.w, 0.f));
    float4* hp = (float4*)(H + (size_t)r * NHID + foff);
    hp[0] = o0;
    hp[1] = o1;
}

// ---------------------------------------------------------------------------
// Fused FC + log_softmax: out[n,c] = logsoftmax(Z[n,:] @ Wfc + bfc)[c]
// 256 threads/block, 64 nodes/block, 4 threads per node (10 classes each)
// ---------------------------------------------------------------------------
__global__ __launch_bounds__(256)
void fc_logsoftmax_kernel(const float* __restrict__ Z, const float* __restrict__ W,
                          const float* __restrict__ bias, float* __restrict__ out, int M) {
    __shared__ float Ws[NHID * NCLASS];   // 40 KB
    __shared__ float bs[NCLASS];

    const int tid = threadIdx.x;
    for (int i = tid; i < NHID * NCLASS; i += 256) Ws[i] = __ldg(&W[i]);
    if (tid < NCLASS) bs[tid] = __ldg(&bias[tid]);
    __syncthreads();

    const int n_raw = blockIdx.x * 64 + (tid >> 2);
    const bool valid = (n_raw < M);
    const int n = valid ? n_raw : (M - 1);   // clamp: keep all lanes alive for shfl
    const int q = tid & 3;                   // class group: classes q*10 .. q*10+9

    float acc[10];
#pragma unroll
    for (int c = 0; c < 10; c++) acc[c] = bs[q * 10 + c];

    const float* zrow = Z + (size_t)n * NHID;
#pragma unroll 4
    for (int k = 0; k < NHID; k++) {
        float zv = __ldg(&zrow[k]);
        const float* wrow = &Ws[k * NCLASS + q * 10];
#pragma unroll
        for (int c = 0; c < 10; c++) acc[c] = fmaf(zv, wrow[c], acc[c]);
    }

    float m = acc[0];
#pragma unroll
    for (int c = 1; c < 10; c++) m = fmaxf(m, acc[c]);
    m = fmaxf(m, __shfl_xor_sync(0xffffffffu, m, 1));
    m = fmaxf(m, __shfl_xor_sync(0xffffffffu, m, 2));

    float s = 0.f;
#pragma unroll
    for (int c = 0; c < 10; c++) s += expf(acc[c] - m);
    s += __shfl_xor_sync(0xffffffffu, s, 1);
    s += __shfl_xor_sync(0xffffffffu, s, 2);

    const float lse = m + logf(s);
    if (valid) {
#pragma unroll
        for (int c = 0; c < 10; c++)
            out[(size_t)n * NCLASS + q * 10 + c] = acc[c] - lse;
    }
}

// ---------------------------------------------------------------------------
// launch
// ---------------------------------------------------------------------------
extern "C" void kernel_launch(void* const* d_in, const int* in_sizes, int n_in,
                              void* d_out, int out_size) {
    const float* x         = (const float*)d_in[0];
    const int*   edge_rows = (const int*)  d_in[1];
    const int*   edge_cols = (const int*)  d_in[2];
    const float* edge_vals = (const float*)d_in[3];
    const float* W1        = (const float*)d_in[4];
    const float* b1        = (const float*)d_in[5];
    const float* W2        = (const float*)d_in[6];
    const float* b2        = (const float*)d_in[7];
    const float* Wfc       = (const float*)d_in[8];
    const float* bfc       = (const float*)d_in[9];
    float* out = (float*)d_out;

    float* bufA;
    float* bufB;
    int*   rowptr;
    cudaGetSymbolAddress((void**)&bufA, g_bufA);
    cudaGetSymbolAddress((void**)&bufB, g_bufB);
    cudaGetSymbolAddress((void**)&rowptr, g_rowptr);

    // 1. CSR row pointers from sorted edge_rows
    build_rowptr_kernel<<<(NNODES + 1 + 255) / 256, 256>>>(edge_rows, NEDGES, rowptr);

    // 2. support1 = x @ W1 + b1   [N, 256]
    {
        dim3 grid(NHID / TBN, (NNODES + TBM - 1) / TBM);
        gemm_tf32_bias<<<grid, 256>>>(x, W1, b1, bufA, NNODES, NHID, NFEAT);
    }
    // 3. h1 = relu(A @ support1)
    spmm_relu_warp<<<(NNODES + 7) / 8, 256>>>(rowptr, edge_cols, edge_vals, bufA, bufB);

    // 4. support2 = h1 @ W2 + b2
    {
        dim3 grid(NHID / TBN, (NNODES + TBM - 1) / TBM);
        gemm_tf32_bias<<<grid, 256>>>(bufB, W2, b2, bufA, NNODES, NHID, NHID);
    }
    // 5. z = relu(A @ support2)
    spmm_relu_warp<<<(NNODES + 7) / 8, 256>>>(rowptr, edge_cols, edge_vals, bufA, bufB);

    // 6. out = log_softmax(z @ Wfc + bfc)
    fc_logsoftmax_kernel<<<(NNODES + 63) / 64, 256>>>(bufB, Wfc, bfc, out, NNODES);
}

// round 6
// speedup vs baseline: 2.3457x; 1.5046x over previous
#include <cuda_runtime.h>
#include <cuda_fp16.h>
#include <math.h>
#include <stdint.h>

// Problem constants (fixed by the reference)
#define NNODES 50000
#define NEDGES 1600000
#define NFEAT  512
#define NHID   256
#define NCLASS 40

// Scratch (allocation-free rule: __device__ globals). Intermediates fp16.
__device__ __align__(16) __half g_bufA[NNODES * NHID];   // 25.6 MB
__device__ __align__(16) __half g_bufB[NNODES * NHID];   // 25.6 MB
__device__ int g_rowptr[NNODES + 1];

__device__ __forceinline__ uint32_t f2tf(float x) {
    uint32_t u;
    asm("cvt.rna.tf32.f32 %0, %1;" : "=r"(u) : "f"(x));
    return u;
}

__device__ __forceinline__ uint32_t pack_h2(float lo, float hi) {
    __half2 h = __floats2half2_rn(lo, hi);
    return *(uint32_t*)&h;
}

// ---------------------------------------------------------------------------
// row_ptr build: edge_rows is sorted -> lower_bound per row
// ---------------------------------------------------------------------------
__global__ void build_rowptr_kernel(const int* __restrict__ rows, int E, int* __restrict__ rp) {
    int r = blockIdx.x * blockDim.x + threadIdx.x;
    if (r > NNODES) return;
    int lo = 0, hi = E;
    while (lo < hi) {
        int mid = (lo + hi) >> 1;
        if (__ldg(&rows[mid]) < r) lo = mid + 1; else hi = mid;
    }
    rp[r] = lo;
}

// ---------------------------------------------------------------------------
// Shared tiling constants (both GEMMs): 128x128 block tile, 8 warps 2x4,
// warp tile 64x32, per-warp 4x4 mma tiles.
// ---------------------------------------------------------------------------
#define TBM 128
#define TBN 128
#define TBK 32
#define AS_STRIDE (TBM + 8)
#define BS_STRIDE (TBN + 8)

// ---------------------------------------------------------------------------
// GEMM1: TF32 mma, A fp32 [M,K], B fp32 [K,N], bias, output fp16
// ---------------------------------------------------------------------------
__global__ __launch_bounds__(256, 1)
void gemm_tf32_bias_f16out(const float* __restrict__ A, const float* __restrict__ B,
                           const float* __restrict__ bias, __half* __restrict__ C,
                           int M, int N, int K) {
    __shared__ uint32_t As[TBK * AS_STRIDE];
    __shared__ uint32_t Bs[TBK * BS_STRIDE];

    const int tid  = threadIdx.x;
    const int warp = tid >> 5;
    const int lane = tid & 31;
    const int g = lane >> 2;
    const int t = lane & 3;
    const int wm = warp & 1;
    const int wn = warp >> 1;

    const int blockRow = blockIdx.y * TBM;
    const int blockCol = blockIdx.x * TBN;

    const int a_m   = tid >> 1;
    const int a_p   = tid & 1;
    const int a_row = blockRow + a_m;
    const bool a_ok = (a_row < M);

    const int b_k  = tid >> 3;
    const int b_nq = tid & 7;

    const int ntiles = K / TBK;

    float4 pa[4], pb[4];
#pragma unroll
    for (int j = 0; j < 4; j++) {
        int kk = 4 * (a_p + 2 * j);
        pa[j] = a_ok ? *(const float4*)&A[(size_t)a_row * K + kk]
                     : make_float4(0.f, 0.f, 0.f, 0.f);
    }
#pragma unroll
    for (int j = 0; j < 4; j++) {
        int nn = 4 * (b_nq + 8 * j);
        pb[j] = *(const float4*)&B[(size_t)b_k * N + blockCol + nn];
    }

    float c[4][4][4];
#pragma unroll
    for (int mt = 0; mt < 4; mt++)
#pragma unroll
        for (int nt = 0; nt < 4; nt++)
#pragma unroll
            for (int q = 0; q < 4; q++) c[mt][nt][q] = 0.f;

    for (int kt = 0; kt < ntiles; kt++) {
#pragma unroll
        for (int j = 0; j < 4; j++) {
            int kk = 4 * (a_p + 2 * j);
            As[(kk + 0) * AS_STRIDE + a_m] = f2tf(pa[j].x);
            As[(kk + 1) * AS_STRIDE + a_m] = f2tf(pa[j].y);
            As[(kk + 2) * AS_STRIDE + a_m] = f2tf(pa[j].z);
            As[(kk + 3) * AS_STRIDE + a_m] = f2tf(pa[j].w);
        }
#pragma unroll
        for (int j = 0; j < 4; j++) {
            int nn = 4 * (b_nq + 8 * j);
            Bs[b_k * BS_STRIDE + nn + 0] = f2tf(pb[j].x);
            Bs[b_k * BS_STRIDE + nn + 1] = f2tf(pb[j].y);
            Bs[b_k * BS_STRIDE + nn + 2] = f2tf(pb[j].z);
            Bs[b_k * BS_STRIDE + nn + 3] = f2tf(pb[j].w);
        }
        __syncthreads();

        if (kt + 1 < ntiles) {
            int k0 = (kt + 1) * TBK;
#pragma unroll
            for (int j = 0; j < 4; j++) {
                int kk = 4 * (a_p + 2 * j);
                pa[j] = a_ok ? *(const float4*)&A[(size_t)a_row * K + k0 + kk]
                             : make_float4(0.f, 0.f, 0.f, 0.f);
            }
#pragma unroll
            for (int j = 0; j < 4; j++) {
                int nn = 4 * (b_nq + 8 * j);
                pb[j] = *(const float4*)&B[(size_t)(k0 + b_k) * N + blockCol + nn];
            }
        }

#pragma unroll
        for (int ks = 0; ks < 4; ks++) {
            const int k0 = ks * 8;
            uint32_t af[4][4];
            uint32_t bf[4][2];
#pragma unroll
            for (int mt = 0; mt < 4; mt++) {
                int m0 = wm * 64 + mt * 16;
                af[mt][0] = As[(k0 + t) * AS_STRIDE + m0 + g];
                af[mt][1] = As[(k0 + t) * AS_STRIDE + m0 + 8 + g];
                af[mt][2] = As[(k0 + t + 4) * AS_STRIDE + m0 + g];
                af[mt][3] = As[(k0 + t + 4) * AS_STRIDE + m0 + 8 + g];
            }
#pragma unroll
            for (int nt = 0; nt < 4; nt++) {
                int n0 = wn * 32 + nt * 8;
                bf[nt][0] = Bs[(k0 + t) * BS_STRIDE + n0 + g];
                bf[nt][1] = Bs[(k0 + t + 4) * BS_STRIDE + n0 + g];
            }
#pragma unroll
            for (int mt = 0; mt < 4; mt++)
#pragma unroll
                for (int nt = 0; nt < 4; nt++) {
                    asm volatile(
                        "mma.sync.aligned.m16n8k8.row.col.f32.tf32.tf32.f32 "
                        "{%0,%1,%2,%3}, {%4,%5,%6,%7}, {%8,%9}, {%0,%1,%2,%3};\n"
                        : "+f"(c[mt][nt][0]), "+f"(c[mt][nt][1]),
                          "+f"(c[mt][nt][2]), "+f"(c[mt][nt][3])
                        : "r"(af[mt][0]), "r"(af[mt][1]), "r"(af[mt][2]), "r"(af[mt][3]),
                          "r"(bf[nt][0]), "r"(bf[nt][1]));
                }
        }
        __syncthreads();
    }

#pragma unroll
    for (int mt = 0; mt < 4; mt++) {
        int r0 = blockRow + wm * 64 + mt * 16 + g;
        int r1 = r0 + 8;
#pragma unroll
        for (int nt = 0; nt < 4; nt++) {
            int col = blockCol + wn * 32 + nt * 8 + 2 * t;
            float bx = __ldg(&bias[col]);
            float by = __ldg(&bias[col + 1]);
            if (r0 < M)
                *(uint32_t*)&C[(size_t)r0 * N + col] = pack_h2(c[mt][nt][0] + bx, c[mt][nt][1] + by);
            if (r1 < M)
                *(uint32_t*)&C[(size_t)r1 * N + col] = pack_h2(c[mt][nt][2] + bx, c[mt][nt][3] + by);
        }
    }
}

// ---------------------------------------------------------------------------
// GEMM2: FP16 mma m16n8k16, A fp16 [M,K], B fp32 [K,N] (converted on load),
// bias, output fp16. Smem holds fp16 PAIRS (k,k+1) packed in uint32,
// indexed [k2][m] / [k2][n].
// ---------------------------------------------------------------------------
#define K2T 16   // TBK/2 pair-entries per tile

__global__ __launch_bounds__(256, 1)
void gemm_f16_bias_f16out(const __half* __restrict__ A, const float* __restrict__ B,
                          const float* __restrict__ bias, __half* __restrict__ C,
                          int M, int N, int K) {
    __shared__ uint32_t As[K2T * AS_STRIDE];
    __shared__ uint32_t Bs[K2T * BS_STRIDE];

    const int tid  = threadIdx.x;
    const int warp = tid >> 5;
    const int lane = tid & 31;
    const int g = lane >> 2;
    const int t = lane & 3;
    const int wm = warp & 1;
    const int wn = warp >> 1;

    const int blockRow = blockIdx.y * TBM;
    const int blockCol = blockIdx.x * TBN;

    // A tile: 128 rows x 32 k fp16 = 8KB; 2 threads/row, 16 fp16 (2x uint4) each
    const int a_m   = tid >> 1;
    const int a_h   = tid & 1;
    const int a_row = blockRow + a_m;
    const bool a_ok = (a_row < M);

    // B tile: 32 k x 128 n fp32 -> packed pairs
    const int b_k2 = tid >> 4;          // 0..15
    const int b_nq = tid & 15;

    const int ntiles = K / TBK;

    uint4 pa[2];
    float4 p0[2], p1[2];
    {
        pa[0] = a_ok ? *(const uint4*)&A[(size_t)a_row * K + 16 * a_h]
                     : make_uint4(0, 0, 0, 0);
        pa[1] = a_ok ? *(const uint4*)&A[(size_t)a_row * K + 16 * a_h + 8]
                     : make_uint4(0, 0, 0, 0);
#pragma unroll
        for (int j = 0; j < 2; j++) {
            int nn = 4 * (b_nq + 16 * j);
            p0[j] = *(const float4*)&B[(size_t)(2 * b_k2) * N + blockCol + nn];
            p1[j] = *(const float4*)&B[(size_t)(2 * b_k2 + 1) * N + blockCol + nn];
        }
    }

    float c[4][4][4];
#pragma unroll
    for (int mt = 0; mt < 4; mt++)
#pragma unroll
        for (int nt = 0; nt < 4; nt++)
#pragma unroll
            for (int q = 0; q < 4; q++) c[mt][nt][q] = 0.f;

    for (int kt = 0; kt < ntiles; kt++) {
        {
            const uint32_t* pu = (const uint32_t*)pa;
#pragma unroll
            for (int i = 0; i < 8; i++)
                As[(8 * a_h + i) * AS_STRIDE + a_m] = pu[i];
#pragma unroll
            for (int j = 0; j < 2; j++) {
                int nn = 4 * (b_nq + 16 * j);
                Bs[b_k2 * BS_STRIDE + nn + 0] = pack_h2(p0[j].x, p1[j].x);
                Bs[b_k2 * BS_STRIDE + nn + 1] = pack_h2(p0[j].y, p1[j].y);
                Bs[b_k2 * BS_STRIDE + nn + 2] = pack_h2(p0[j].z, p1[j].z);
                Bs[b_k2 * BS_STRIDE + nn + 3] = pack_h2(p0[j].w, p1[j].w);
            }
        }
        __syncthreads();

        if (kt + 1 < ntiles) {
            int k0 = (kt + 1) * TBK;
            pa[0] = a_ok ? *(const uint4*)&A[(size_t)a_row * K + k0 + 16 * a_h]
                         : make_uint4(0, 0, 0, 0);
            pa[1] = a_ok ? *(const uint4*)&A[(size_t)a_row * K + k0 + 16 * a_h + 8]
                         : make_uint4(0, 0, 0, 0);
#pragma unroll
            for (int j = 0; j < 2; j++) {
                int nn = 4 * (b_nq + 16 * j);
                p0[j] = *(const float4*)&B[(size_t)(k0 + 2 * b_k2) * N + blockCol + nn];
                p1[j] = *(const float4*)&B[(size_t)(k0 + 2 * b_k2 + 1) * N + blockCol + nn];
            }
        }

#pragma unroll
        for (int ks = 0; ks < 2; ks++) {
            const int k2b = ks * 8;
            uint32_t af[4][4];
            uint32_t bf[4][2];
#pragma unroll
            for (int mt = 0; mt < 4; mt++) {
                int m0 = wm * 64 + mt * 16;
                af[mt][0] = As[(k2b + t) * AS_STRIDE + m0 + g];
                af[mt][1] = As[(k2b + t) * AS_STRIDE + m0 + 8 + g];
                af[mt][2] = As[(k2b + t + 4) * AS_STRIDE + m0 + g];
                af[mt][3] = As[(k2b + t + 4) * AS_STRIDE + m0 + 8 + g];
            }
#pragma unroll
            for (int nt = 0; nt < 4; nt++) {
                int n0 = wn * 32 + nt * 8;
                bf[nt][0] = Bs[(k2b + t) * BS_STRIDE + n0 + g];
                bf[nt][1] = Bs[(k2b + t + 4) * BS_STRIDE + n0 + g];
            }
#pragma unroll
            for (int mt = 0; mt < 4; mt++)
#pragma unroll
                for (int nt = 0; nt < 4; nt++) {
                    asm volatile(
                        "mma.sync.aligned.m16n8k16.row.col.f32.f16.f16.f32 "
                        "{%0,%1,%2,%3}, {%4,%5,%6,%7}, {%8,%9}, {%0,%1,%2,%3};\n"
                        : "+f"(c[mt][nt][0]), "+f"(c[mt][nt][1]),
                          "+f"(c[mt][nt][2]), "+f"(c[mt][nt][3])
                        : "r"(af[mt][0]), "r"(af[mt][1]), "r"(af[mt][2]), "r"(af[mt][3]),
                          "r"(bf[nt][0]), "r"(bf[nt][1]));
                }
        }
        __syncthreads();
    }

#pragma unroll
    for (int mt = 0; mt < 4; mt++) {
        int r0 = blockRow + wm * 64 + mt * 16 + g;
        int r1 = r0 + 8;
#pragma unroll
        for (int nt = 0; nt < 4; nt++) {
            int col = blockCol + wn * 32 + nt * 8 + 2 * t;
            float bx = __ldg(&bias[col]);
            float by = __ldg(&bias[col + 1]);
            if (r0 < M)
                *(uint32_t*)&C[(size_t)r0 * N + col] = pack_h2(c[mt][nt][0] + bx, c[mt][nt][1] + by);
            if (r1 < M)
                *(uint32_t*)&C[(size_t)r1 * N + col] = pack_h2(c[mt][nt][2] + bx, c[mt][nt][3] + by);
        }
    }
}

// ---------------------------------------------------------------------------
// SpMM + ReLU (fp16 in/out, fp32 accumulate): one warp per row;
// lane stages one edge; shfl-broadcast; 8 fp16 feats/lane (one LDG.128)
// ---------------------------------------------------------------------------
__global__ __launch_bounds__(256)
void spmm_relu_warp_f16(const int* __restrict__ rp, const int* __restrict__ cols,
                        const float* __restrict__ vals,
                        const __half* __restrict__ S,
                        __half* __restrict__ H) {
    const int warp = threadIdx.x >> 5;
    const int lane = threadIdx.x & 31;
    const int r = blockIdx.x * 8 + warp;
    if (r >= NNODES) return;

    const int start = rp[r];
    const int end   = rp[r + 1];
    const int foff  = lane * 8;

    float acc[8];
#pragma unroll
    for (int i = 0; i < 8; i++) acc[i] = 0.f;

    for (int base = start; base < end; base += 32) {
        int idx = base + lane;
        int   cc = 0;
        float vv = 0.f;
        if (idx < end) {
            cc = __ldg(&cols[idx]);
            vv = __ldg(&vals[idx]);
        }
        const int n = min(32, end - base);
#pragma unroll 4
        for (int j = 0; j < n; j++) {
            int   col = __shfl_sync(0xffffffffu, cc, j);
            float v   = __shfl_sync(0xffffffffu, vv, j);
            uint4 u = __ldg((const uint4*)(S + (size_t)col * NHID + foff));
            const __half2* hp = (const __half2*)&u;
            float2 f0 = __half22float2(hp[0]);
            float2 f1 = __half22float2(hp[1]);
            float2 f2 = __half22float2(hp[2]);
            float2 f3 = __half22float2(hp[3]);
            acc[0] = fmaf(v, f0.x, acc[0]);
            acc[1] = fmaf(v, f0.y, acc[1]);
            acc[2] = fmaf(v, f1.x, acc[2]);
            acc[3] = fmaf(v, f1.y, acc[3]);
            acc[4] = fmaf(v, f2.x, acc[4]);
            acc[5] = fmaf(v, f2.y, acc[5]);
            acc[6] = fmaf(v, f3.x, acc[6]);
            acc[7] = fmaf(v, f3.y, acc[7]);
        }
    }

    uint4 o;
    uint32_t* op = (uint32_t*)&o;
#pragma unroll
    for (int i = 0; i < 4; i++)
        op[i] = pack_h2(fmaxf(acc[2 * i], 0.f), fmaxf(acc[2 * i + 1], 0.f));
    *(uint4*)(H + (size_t)r * NHID + foff) = o;
}

// ---------------------------------------------------------------------------
// Fused FC + log_softmax: out[n,c] = logsoftmax(Z[n,:] @ Wfc + bfc)[c]
// Z is fp16. 256 threads/block, 64 nodes/block, 4 threads/node, 10 classes each
// ---------------------------------------------------------------------------
__global__ __launch_bounds__(256)
void fc_logsoftmax_kernel(const __half* __restrict__ Z, const float* __restrict__ W,
                          const float* __restrict__ bias, float* __restrict__ out, int M) {
    __shared__ float Ws[NHID * NCLASS];   // 40 KB
    __shared__ float bs[NCLASS];

    const int tid = threadIdx.x;
    for (int i = tid; i < NHID * NCLASS; i += 256) Ws[i] = __ldg(&W[i]);
    if (tid < NCLASS) bs[tid] = __ldg(&bias[tid]);
    __syncthreads();

    const int n_raw = blockIdx.x * 64 + (tid >> 2);
    const bool valid = (n_raw < M);
    const int n = valid ? n_raw : (M - 1);
    const int q = tid & 3;

    float acc[10];
#pragma unroll
    for (int c = 0; c < 10; c++) acc[c] = bs[q * 10 + c];

    const __half2* zrow = (const __half2*)(Z + (size_t)n * NHID);
#pragma unroll 4
    for (int k2 = 0; k2 < NHID / 2; k2++) {
        float2 zv = __half22float2(__ldg(&zrow[k2]));
        const float* w0 = &Ws[(2 * k2) * NCLASS + q * 10];
        const float* w1 = w0 + NCLASS;
#pragma unroll
        for (int c = 0; c < 10; c++) {
            acc[c] = fmaf(zv.x, w0[c], acc[c]);
            acc[c] = fmaf(zv.y, w1[c], acc[c]);
        }
    }

    float m = acc[0];
#pragma unroll
    for (int c = 1; c < 10; c++) m = fmaxf(m, acc[c]);
    m = fmaxf(m, __shfl_xor_sync(0xffffffffu, m, 1));
    m = fmaxf(m, __shfl_xor_sync(0xffffffffu, m, 2));

    float s = 0.f;
#pragma unroll
    for (int c = 0; c < 10; c++) s += expf(acc[c] - m);
    s += __shfl_xor_sync(0xffffffffu, s, 1);
    s += __shfl_xor_sync(0xffffffffu, s, 2);

    const float lse = m + logf(s);
    if (valid) {
#pragma unroll
        for (int c = 0; c < 10; c++)
            out[(size_t)n * NCLASS + q * 10 + c] = acc[c] - lse;
    }
}

// ---------------------------------------------------------------------------
// launch
// ---------------------------------------------------------------------------
extern "C" void kernel_launch(void* const* d_in, const int* in_sizes, int n_in,
                              void* d_out, int out_size) {
    const float* x         = (const float*)d_in[0];
    const int*   edge_rows = (const int*)  d_in[1];
    const int*   edge_cols = (const int*)  d_in[2];
    const float* edge_vals = (const float*)d_in[3];
    const float* W1        = (const float*)d_in[4];
    const float* b1        = (const float*)d_in[5];
    const float* W2        = (const float*)d_in[6];
    const float* b2        = (const float*)d_in[7];
    const float* Wfc       = (const float*)d_in[8];
    const float* bfc       = (const float*)d_in[9];
    float* out = (float*)d_out;

    __half* bufA;
    __half* bufB;
    int* rowptr;
    cudaGetSymbolAddress((void**)&bufA, g_bufA);
    cudaGetSymbolAddress((void**)&bufB, g_bufB);
    cudaGetSymbolAddress((void**)&rowptr, g_rowptr);

    // 1. CSR row pointers from sorted edge_rows
    build_rowptr_kernel<<<(NNODES + 1 + 255) / 256, 256>>>(edge_rows, NEDGES, rowptr);

    // 2. support1 = x @ W1 + b1  (tf32 mma, fp16 out)
    {
        dim3 grid(NHID / TBN, (NNODES + TBM - 1) / TBM);
        gemm_tf32_bias_f16out<<<grid, 256>>>(x, W1, b1, bufA, NNODES, NHID, NFEAT);
    }
    // 3. h1 = relu(A @ support1)  (fp16 gather, fp32 accum, fp16 out)
    spmm_relu_warp_f16<<<(NNODES + 7) / 8, 256>>>(rowptr, edge_cols, edge_vals, bufA, bufB);

    // 4. support2 = h1 @ W2 + b2  (fp16 mma, fp16 out)
    {
        dim3 grid(NHID / TBN, (NNODES + TBM - 1) / TBM);
        gemm_f16_bias_f16out<<<grid, 256>>>(bufB, W2, b2, bufA, NNODES, NHID, NHID);
    }
    // 5. z = relu(A @ support2)
    spmm_relu_warp_f16<<<(NNODES + 7) / 8, 256>>>(rowptr, edge_cols, edge_vals, bufA, bufB);

    // 6. out = log_softmax(z @ Wfc + bfc)
    fc_logsoftmax_kernel<<<(NNODES + 63) / 64, 256>>>(bufB, Wfc, bfc, out, NNODES);
}

// round 9
// speedup vs baseline: 2.3780x; 1.0137x over previous
#include <cuda_runtime.h>
#include <cuda_fp16.h>
#include <math.h>
#include <stdint.h>

// Problem constants (fixed by the reference)
#define NNODES 50000
#define NEDGES 1600000
#define NFEAT  512
#define NHID   256
#define NCLASS 40

// Scratch (allocation-free rule: __device__ globals).
// Gathered matrices (S1, S2) and z are fp16; h1 (linear-read only) is fp32.
__device__ __align__(16) __half g_bufA[NNODES * NHID];   // 25.6 MB (S1, then S2)
__device__ __align__(16) __half g_bufB[NNODES * NHID];   // 25.6 MB (z)
__device__ __align__(16) float  g_bufC[NNODES * NHID];   // 51.2 MB (h1)
__device__ int g_rowptr[NNODES + 1];

__device__ __forceinline__ uint32_t pack_h2(float lo, float hi) {
    __half2 h = __floats2half2_rn(lo, hi);
    return *(uint32_t*)&h;
}

// unbiased tf32 rounding (round-to-nearest) — REQUIRED: RZ truncation is biased
// and blows up the K-long reductions (measured: rel_err 1.0e-3 vs 1.6e-4).
__device__ __forceinline__ uint32_t f2tf(uint32_t raw) {
    uint32_t u;
    asm("cvt.rna.tf32.f32 %0, %1;" : "=r"(u) : "r"(raw));
    return u;
}

__device__ __forceinline__ void cp_async16(uint32_t dst, const void* src, int src_bytes) {
    asm volatile("cp.async.cg.shared.global [%0], [%1], 16, %2;\n"
                 :: "r"(dst), "l"(src), "r"(src_bytes));
}
__device__ __forceinline__ void cp_commit() {
    asm volatile("cp.async.commit_group;\n" ::: "memory");
}
__device__ __forceinline__ void cp_wait1() {
    asm volatile("cp.async.wait_group 1;\n" ::: "memory");
}

// ---------------------------------------------------------------------------
// row_ptr build: edge_rows is sorted -> lower_bound per row
// ---------------------------------------------------------------------------
__global__ void build_rowptr_kernel(const int* __restrict__ rows, int E, int* __restrict__ rp) {
    int r = blockIdx.x * blockDim.x + threadIdx.x;
    if (r > NNODES) return;
    int lo = 0, hi = E;
    while (lo < hi) {
        int mid = (lo + hi) >> 1;
        if (__ldg(&rows[mid]) < r) lo = mid + 1; else hi = mid;
    }
    rp[r] = lo;
}

// ---------------------------------------------------------------------------
// Unified TF32 GEMM + bias -> fp16 out, cp.async double-buffered, 2 CTA/SM.
// C[M,N] = A[M,K] @ B[K,N] + bias.  Tiles staged raw fp32; fragments are
// rna-rounded to tf32 in registers right before the MMA.
// Block tile 128x128, TBK=16. 8 warps 2(m)x4(n), warp tile 64x32, 4x4 mma tiles.
// As[m][k] stride 20 (banks 20g+t distinct); Bs[k][n] stride 136 (8t+g distinct).
// ---------------------------------------------------------------------------
#define TBM 128
#define TBN 128
#define TBK 16
#define ASTR 20
#define BSTR 136

__global__ __launch_bounds__(256, 2)
void gemm_tf32_async(const float* __restrict__ A, const float* __restrict__ B,
                     const float* __restrict__ bias, __half* __restrict__ C,
                     int M, int N, int K) {
    __shared__ float As[2][TBM * ASTR];   // 2 * 10240 B
    __shared__ float Bs[2][TBK * BSTR];   // 2 * 8704 B

    const int tid  = threadIdx.x;
    const int warp = tid >> 5;
    const int lane = tid & 31;
    const int g = lane >> 2;
    const int t = lane & 3;
    const int wm = warp & 1;
    const int wn = warp >> 1;

    const int blockRow = blockIdx.y * TBM;
    const int blockCol = blockIdx.x * TBN;
    const int ntiles = K / TBK;

    uint32_t as_base = (uint32_t)__cvta_generic_to_shared(&As[0][0]);
    uint32_t bs_base = (uint32_t)__cvta_generic_to_shared(&Bs[0][0]);
    const uint32_t as_sz = TBM * ASTR * 4;
    const uint32_t bs_sz = TBK * BSTR * 4;

    // --- async tile loader: 2 x 16B chunks per thread per tile side ---
    auto load_tile = [&](int kt, int b) {
        int k0 = kt * TBK;
#pragma unroll
        for (int j = 0; j < 2; j++) {
            int c   = tid + j * 256;
            int row = c >> 2;                 // 0..127
            int f   = (c & 3) * 4;            // 0,4,8,12
            int grow = blockRow + row;
            int ok = (grow < M) ? 16 : 0;
            int gr = (grow < M) ? grow : (M - 1);
            cp_async16(as_base + b * as_sz + (row * ASTR + f) * 4,
                       A + (size_t)gr * K + k0 + f, ok);
        }
#pragma unroll
        for (int j = 0; j < 2; j++) {
            int c   = tid + j * 256;
            int row = c >> 5;                 // 0..15
            int f   = (c & 31) * 4;           // 0..124
            cp_async16(bs_base + b * bs_sz + (row * BSTR + f) * 4,
                       B + (size_t)(k0 + row) * N + blockCol + f, 16);
        }
    };

    float acc[4][4][4];
#pragma unroll
    for (int mt = 0; mt < 4; mt++)
#pragma unroll
        for (int nt = 0; nt < 4; nt++)
#pragma unroll
            for (int q = 0; q < 4; q++) acc[mt][nt][q] = 0.f;

    load_tile(0, 0);
    cp_commit();

    for (int kt = 0; kt < ntiles; kt++) {
        if (kt + 1 < ntiles) load_tile(kt + 1, (kt + 1) & 1);
        cp_commit();                 // empty group on last iter keeps wait math fixed
        cp_wait1();                  // tile kt resident
        __syncthreads();

        const uint32_t* as = (const uint32_t*)As[kt & 1];
        const uint32_t* bs = (const uint32_t*)Bs[kt & 1];

#pragma unroll
        for (int ks = 0; ks < 2; ks++) {
            const int k0 = ks * 8;
            uint32_t af[4][4];
            uint32_t bf[4][2];
#pragma unroll
            for (int mt = 0; mt < 4; mt++) {
                int m0 = wm * 64 + mt * 16;
                af[mt][0] = f2tf(as[(m0 + g) * ASTR + k0 + t]);
                af[mt][1] = f2tf(as[(m0 + 8 + g) * ASTR + k0 + t]);
                af[mt][2] = f2tf(as[(m0 + g) * ASTR + k0 + t + 4]);
                af[mt][3] = f2tf(as[(m0 + 8 + g) * ASTR + k0 + t + 4]);
            }
#pragma unroll
            for (int nt = 0; nt < 4; nt++) {
                int n0 = wn * 32 + nt * 8;
                bf[nt][0] = f2tf(bs[(k0 + t) * BSTR + n0 + g]);
                bf[nt][1] = f2tf(bs[(k0 + t + 4) * BSTR + n0 + g]);
            }
#pragma unroll
            for (int mt = 0; mt < 4; mt++)
#pragma unroll
                for (int nt = 0; nt < 4; nt++) {
                    asm volatile(
                        "mma.sync.aligned.m16n8k8.row.col.f32.tf32.tf32.f32 "
                        "{%0,%1,%2,%3}, {%4,%5,%6,%7}, {%8,%9}, {%0,%1,%2,%3};\n"
                        : "+f"(acc[mt][nt][0]), "+f"(acc[mt][nt][1]),
                          "+f"(acc[mt][nt][2]), "+f"(acc[mt][nt][3])
                        : "r"(af[mt][0]), "r"(af[mt][1]), "r"(af[mt][2]), "r"(af[mt][3]),
                          "r"(bf[nt][0]), "r"(bf[nt][1]));
                }
        }
        __syncthreads();
    }

    // epilogue: + bias, fp16 pack, guarded store
#pragma unroll
    for (int mt = 0; mt < 4; mt++) {
        int r0 = blockRow + wm * 64 + mt * 16 + g;
        int r1 = r0 + 8;
#pragma unroll
        for (int nt = 0; nt < 4; nt++) {
            int col = blockCol + wn * 32 + nt * 8 + 2 * t;
            float bx = __ldg(&bias[col]);
            float by = __ldg(&bias[col + 1]);
            if (r0 < M)
                *(uint32_t*)&C[(size_t)r0 * N + col] = pack_h2(acc[mt][nt][0] + bx, acc[mt][nt][1] + by);
            if (r1 < M)
                *(uint32_t*)&C[(size_t)r1 * N + col] = pack_h2(acc[mt][nt][2] + bx, acc[mt][nt][3] + by);
        }
    }
}

// ---------------------------------------------------------------------------
// SpMM + ReLU, fp16 gather source, fp32 accumulate, templated output type.
// One warp per row; full 32-edge batches (fixed trip count -> batched LDGs),
// dynamic tail separate. 8 fp16 feats/lane via one LDG.128.
// ---------------------------------------------------------------------------
template <typename OutT>
__global__ __launch_bounds__(256)
void spmm_relu(const int* __restrict__ rp, const int* __restrict__ cols,
               const float* __restrict__ vals, const __half* __restrict__ S,
               OutT* __restrict__ H) {
    const int warp = threadIdx.x >> 5;
    const int lane = threadIdx.x & 31;
    const int r = blockIdx.x * 8 + warp;
    if (r >= NNODES) return;

    const int start = rp[r];
    const int end   = rp[r + 1];
    const int foff  = lane * 8;

    float acc[8];
#pragma unroll
    for (int i = 0; i < 8; i++) acc[i] = 0.f;

    int base = start;
    // full batches: fixed 32-trip inner loop
    for (; base + 32 <= end; base += 32) {
        int   cc = __ldg(&cols[base + lane]);
        float vv = __ldg(&vals[base + lane]);
#pragma unroll 8
        for (int j = 0; j < 32; j++) {
            int   col = __shfl_sync(0xffffffffu, cc, j);
            float v   = __shfl_sync(0xffffffffu, vv, j);
            uint4 u = __ldg((const uint4*)(S + (size_t)col * NHID + foff));
            const __half2* hp = (const __half2*)&u;
            float2 f0 = __half22float2(hp[0]);
            float2 f1 = __half22float2(hp[1]);
            float2 f2 = __half22float2(hp[2]);
            float2 f3 = __half22float2(hp[3]);
            acc[0] = fmaf(v, f0.x, acc[0]);
            acc[1] = fmaf(v, f0.y, acc[1]);
            acc[2] = fmaf(v, f1.x, acc[2]);
            acc[3] = fmaf(v, f1.y, acc[3]);
            acc[4] = fmaf(v, f2.x, acc[4]);
            acc[5] = fmaf(v, f2.y, acc[5]);
            acc[6] = fmaf(v, f3.x, acc[6]);
            acc[7] = fmaf(v, f3.y, acc[7]);
        }
    }
    // tail
    int rem = end - base;
    if (rem > 0) {
        int   cc = 0;
        float vv = 0.f;
        if (lane < rem) {
            cc = __ldg(&cols[base + lane]);
            vv = __ldg(&vals[base + lane]);
        }
        for (int j = 0; j < rem; j++) {
            int   col = __shfl_sync(0xffffffffu, cc, j);
            float v   = __shfl_sync(0xffffffffu, vv, j);
            uint4 u = __ldg((const uint4*)(S + (size_t)col * NHID + foff));
            const __half2* hp = (const __half2*)&u;
            float2 f0 = __half22float2(hp[0]);
            float2 f1 = __half22float2(hp[1]);
            float2 f2 = __half22float2(hp[2]);
            float2 f3 = __half22float2(hp[3]);
            acc[0] = fmaf(v, f0.x, acc[0]);
            acc[1] = fmaf(v, f0.y, acc[1]);
            acc[2] = fmaf(v, f1.x, acc[2]);
            acc[3] = fmaf(v, f1.y, acc[3]);
            acc[4] = fmaf(v, f2.x, acc[4]);
            acc[5] = fmaf(v, f2.y, acc[5]);
            acc[6] = fmaf(v, f3.x, acc[6]);
            acc[7] = fmaf(v, f3.y, acc[7]);
        }
    }

    if constexpr (sizeof(OutT) == 2) {
        uint4 o;
        uint32_t* op = (uint32_t*)&o;
#pragma unroll
        for (int i = 0; i < 4; i++)
            op[i] = pack_h2(fmaxf(acc[2 * i], 0.f), fmaxf(acc[2 * i + 1], 0.f));
        *(uint4*)((__half*)H + (size_t)r * NHID + foff) = o;
    } else {
        float4 o0 = make_float4(fmaxf(acc[0], 0.f), fmaxf(acc[1], 0.f),
                                fmaxf(acc[2], 0.f), fmaxf(acc[3], 0.f));
        float4 o1 = make_float4(fmaxf(acc[4], 0.f), fmaxf(acc[5], 0.f),
                                fmaxf(acc[6], 0.f), fmaxf(acc[7], 0.f));
        float4* hp = (float4*)((float*)H + (size_t)r * NHID + foff);
        hp[0] = o0;
        hp[1] = o1;
    }
}

// ---------------------------------------------------------------------------
// Fused FC + log_softmax: out[n,c] = logsoftmax(Z[n,:] @ Wfc + bfc)[c]
// Z is fp16. 256 threads/block, 64 nodes/block, 4 threads/node, 10 classes each
// ---------------------------------------------------------------------------
__global__ __launch_bounds__(256)
void fc_logsoftmax_kernel(const __half* __restrict__ Z, const float* __restrict__ W,
                          const float* __restrict__ bias, float* __restrict__ out, int M) {
    __shared__ float Ws[NHID * NCLASS];   // 40 KB
    __shared__ float bs[NCLASS];

    const int tid = threadIdx.x;
    for (int i = tid; i < NHID * NCLASS; i += 256) Ws[i] = __ldg(&W[i]);
    if (tid < NCLASS) bs[tid] = __ldg(&bias[tid]);
    __syncthreads();

    const int n_raw = blockIdx.x * 64 + (tid >> 2);
    const bool valid = (n_raw < M);
    const int n = valid ? n_raw : (M - 1);
    const int q = tid & 3;

    float acc[10];
#pragma unroll
    for (int c = 0; c < 10; c++) acc[c] = bs[q * 10 + c];

    const __half2* zrow = (const __half2*)(Z + (size_t)n * NHID);
#pragma unroll 4
    for (int k2 = 0; k2 < NHID / 2; k2++) {
        float2 zv = __half22float2(__ldg(&zrow[k2]));
        const float* w0 = &Ws[(2 * k2) * NCLASS + q * 10];
        const float* w1 = w0 + NCLASS;
#pragma unroll
        for (int c = 0; c < 10; c++) {
            acc[c] = fmaf(zv.x, w0[c], acc[c]);
            acc[c] = fmaf(zv.y, w1[c], acc[c]);
        }
    }

    float m = acc[0];
#pragma unroll
    for (int c = 1; c < 10; c++) m = fmaxf(m, acc[c]);
    m = fmaxf(m, __shfl_xor_sync(0xffffffffu, m, 1));
    m = fmaxf(m, __shfl_xor_sync(0xffffffffu, m, 2));

    float s = 0.f;
#pragma unroll
    for (int c = 0; c < 10; c++) s += expf(acc[c] - m);
    s += __shfl_xor_sync(0xffffffffu, s, 1);
    s += __shfl_xor_sync(0xffffffffu, s, 2);

    const float lse = m + logf(s);
    if (valid) {
#pragma unroll
        for (int c = 0; c < 10; c++)
            out[(size_t)n * NCLASS + q * 10 + c] = acc[c] - lse;
    }
}

// ---------------------------------------------------------------------------
// launch
// ---------------------------------------------------------------------------
extern "C" void kernel_launch(void* const* d_in, const int* in_sizes, int n_in,
                              void* d_out, int out_size) {
    const float* x         = (const float*)d_in[0];
    const int*   edge_rows = (const int*)  d_in[1];
    const int*   edge_cols = (const int*)  d_in[2];
    const float* edge_vals = (const float*)d_in[3];
    const float* W1        = (const float*)d_in[4];
    const float* b1        = (const float*)d_in[5];
    const float* W2        = (const float*)d_in[6];
    const float* b2        = (const float*)d_in[7];
    const float* Wfc       = (const float*)d_in[8];
    const float* bfc       = (const float*)d_in[9];
    float* out = (float*)d_out;

    __half* bufA;
    __half* bufB;
    float*  bufC;
    int* rowptr;
    cudaGetSymbolAddress((void**)&bufA, g_bufA);
    cudaGetSymbolAddress((void**)&bufB, g_bufB);
    cudaGetSymbolAddress((void**)&bufC, g_bufC);
    cudaGetSymbolAddress((void**)&rowptr, g_rowptr);

    // 1. CSR row pointers from sorted edge_rows
    build_rowptr_kernel<<<(NNODES + 1 + 255) / 256, 256>>>(edge_rows, NEDGES, rowptr);

    dim3 ggrid(NHID / TBN, (NNODES + TBM - 1) / TBM);

    // 2. S1 = x @ W1 + b1   (tf32 async GEMM, fp16 out)
    gemm_tf32_async<<<ggrid, 256>>>(x, W1, b1, bufA, NNODES, NHID, NFEAT);

    // 3. h1 = relu(A @ S1)  (fp16 gather, fp32 out)
    spmm_relu<float><<<(NNODES + 7) / 8, 256>>>(rowptr, edge_cols, edge_vals, bufA, bufC);

    // 4. S2 = h1 @ W2 + b2  (tf32 async GEMM, fp16 out)
    gemm_tf32_async<<<ggrid, 256>>>(bufC, W2, b2, bufA, NNODES, NHID, NHID);

    // 5. z = relu(A @ S2)   (fp16 gather, fp16 out)
    spmm_relu<__half><<<(NNODES + 7) / 8, 256>>>(rowptr, edge_cols, edge_vals, bufA, bufB);

    // 6. out = log_softmax(z @ Wfc + bfc)
    fc_logsoftmax_kernel<<<(NNODES + 63) / 64, 256>>>(bufB, Wfc, bfc, out, NNODES);
}

// round 10
// speedup vs baseline: 2.4590x; 1.0341x over previous
#include <cuda_runtime.h>
#include <cuda_fp16.h>
#include <math.h>
#include <stdint.h>

// Problem constants (fixed by the reference)
#define NNODES 50000
#define NEDGES 1600000
#define NFEAT  512
#define NHID   256
#define NCLASS 40

// Scratch (allocation-free rule: __device__ globals).
// Gathered matrices (S1, S2) and z are fp16; h1 (linear-read only) is fp32
// pre-rounded to tf32 at store. Weights pre-rounded to tf32 once.
__device__ __align__(16) __half g_bufA[NNODES * NHID];   // 25.6 MB (S1, then S2)
__device__ __align__(16) __half g_bufB[NNODES * NHID];   // 25.6 MB (z)
__device__ __align__(16) float  g_bufC[NNODES * NHID];   // 51.2 MB (h1, tf32-rounded)
__device__ __align__(16) float  g_w1t[NFEAT * NHID];     // 0.5 MB  (W1 tf32-rounded)
__device__ __align__(16) float  g_w2t[NHID * NHID];      // 0.25 MB (W2 tf32-rounded)
__device__ int g_rowptr[NNODES + 1];

__device__ __forceinline__ uint32_t pack_h2(float lo, float hi) {
    __half2 h = __floats2half2_rn(lo, hi);
    return *(uint32_t*)&h;
}

// unbiased tf32 rounding (round-to-nearest) — REQUIRED: RZ truncation is biased
// and blows up the K-long reductions (measured: rel_err 1.0e-3 vs 1.6e-4).
// mma.tf32 truncation is the IDENTITY on pre-rounded values, so rounding once
// at the producer == rounding at fragment load.
__device__ __forceinline__ uint32_t f2tf(uint32_t raw) {
    uint32_t u;
    asm("cvt.rna.tf32.f32 %0, %1;" : "=r"(u) : "r"(raw));
    return u;
}
__device__ __forceinline__ float f2tf_f(float x) {
    return __uint_as_float(f2tf(__float_as_uint(x)));
}

__device__ __forceinline__ void cp_async16(uint32_t dst, const void* src, int src_bytes) {
    asm volatile("cp.async.cg.shared.global [%0], [%1], 16, %2;\n"
                 :: "r"(dst), "l"(src), "r"(src_bytes));
}
__device__ __forceinline__ void cp_commit() {
    asm volatile("cp.async.commit_group;\n" ::: "memory");
}
__device__ __forceinline__ void cp_wait1() {
    asm volatile("cp.async.wait_group 1;\n" ::: "memory");
}

// ---------------------------------------------------------------------------
// Pre-round weights to tf32 (rna) once per call.
// ---------------------------------------------------------------------------
__global__ void round_weights_kernel(const float* __restrict__ W1, const float* __restrict__ W2,
                                     float* __restrict__ w1t, float* __restrict__ w2t) {
    int i = blockIdx.x * blockDim.x + threadIdx.x;
    if (i < NFEAT * NHID) w1t[i] = f2tf_f(__ldg(&W1[i]));
    if (i < NHID * NHID)  w2t[i] = f2tf_f(__ldg(&W2[i]));
}

// ---------------------------------------------------------------------------
// row_ptr build: edge_rows is sorted -> lower_bound per row
// ---------------------------------------------------------------------------
__global__ void build_rowptr_kernel(const int* __restrict__ rows, int E, int* __restrict__ rp) {
    int r = blockIdx.x * blockDim.x + threadIdx.x;
    if (r > NNODES) return;
    int lo = 0, hi = E;
    while (lo < hi) {
        int mid = (lo + hi) >> 1;
        if (__ldg(&rows[mid]) < r) lo = mid + 1; else hi = mid;
    }
    rp[r] = lo;
}

// ---------------------------------------------------------------------------
// Unified TF32 GEMM + bias -> fp16 out, cp.async double-buffered, 2 CTA/SM.
// C[M,N] = A[M,K] @ B[K,N] + bias.  B is ALWAYS pre-rounded tf32 (raw feed).
// A fragments rna-rounded in registers iff CVT_A (x is raw fp32); otherwise
// A is pre-rounded by its producer (h1 from SpMM) and fed raw.
// Block tile 128x128, TBK=16. 8 warps 2(m)x4(n), warp tile 64x32, 4x4 mma tiles.
// As[m][k] stride 20 (banks 20g+t distinct); Bs[k][n] stride 136 (8t+g distinct).
// ---------------------------------------------------------------------------
#define TBM 128
#define TBN 128
#define TBK 16
#define ASTR 20
#define BSTR 136

template <bool CVT_A>
__global__ __launch_bounds__(256, 2)
void gemm_tf32_async(const float* __restrict__ A, const float* __restrict__ B,
                     const float* __restrict__ bias, __half* __restrict__ C,
                     int M, int N, int K) {
    __shared__ float As[2][TBM * ASTR];   // 2 * 10240 B
    __shared__ float Bs[2][TBK * BSTR];   // 2 * 8704 B

    const int tid  = threadIdx.x;
    const int warp = tid >> 5;
    const int lane = tid & 31;
    const int g = lane >> 2;
    const int t = lane & 3;
    const int wm = warp & 1;
    const int wn = warp >> 1;

    const int blockRow = blockIdx.y * TBM;
    const int blockCol = blockIdx.x * TBN;
    const int ntiles = K / TBK;

    uint32_t as_base = (uint32_t)__cvta_generic_to_shared(&As[0][0]);
    uint32_t bs_base = (uint32_t)__cvta_generic_to_shared(&Bs[0][0]);
    const uint32_t as_sz = TBM * ASTR * 4;
    const uint32_t bs_sz = TBK * BSTR * 4;

    // --- async tile loader: 2 x 16B chunks per thread per tile side ---
    auto load_tile = [&](int kt, int b) {
        int k0 = kt * TBK;
#pragma unroll
        for (int j = 0; j < 2; j++) {
            int c   = tid + j * 256;
            int row = c >> 2;                 // 0..127
            int f   = (c & 3) * 4;            // 0,4,8,12
            int grow = blockRow + row;
            int ok = (grow < M) ? 16 : 0;
            int gr = (grow < M) ? grow : (M - 1);
            cp_async16(as_base + b * as_sz + (row * ASTR + f) * 4,
                       A + (size_t)gr * K + k0 + f, ok);
        }
#pragma unroll
        for (int j = 0; j < 2; j++) {
            int c   = tid + j * 256;
            int row = c >> 5;                 // 0..15
            int f   = (c & 31) * 4;           // 0..124
            cp_async16(bs_base + b * bs_sz + (row * BSTR + f) * 4,
                       B + (size_t)(k0 + row) * N + blockCol + f, 16);
        }
    };

    float acc[4][4][4];
#pragma unroll
    for (int mt = 0; mt < 4; mt++)
#pragma unroll
        for (int nt = 0; nt < 4; nt++)
#pragma unroll
            for (int q = 0; q < 4; q++) acc[mt][nt][q] = 0.f;

    load_tile(0, 0);
    cp_commit();

    for (int kt = 0; kt < ntiles; kt++) {
        if (kt + 1 < ntiles) load_tile(kt + 1, (kt + 1) & 1);
        cp_commit();                 // empty group on last iter keeps wait math fixed
        cp_wait1();                  // tile kt resident
        __syncthreads();

        const uint32_t* as = (const uint32_t*)As[kt & 1];
        const uint32_t* bs = (const uint32_t*)Bs[kt & 1];

#pragma unroll
        for (int ks = 0; ks < 2; ks++) {
            const int k0 = ks * 8;
            uint32_t af[4][4];
            uint32_t bf[4][2];
#pragma unroll
            for (int mt = 0; mt < 4; mt++) {
                int m0 = wm * 64 + mt * 16;
                uint32_t a0 = as[(m0 + g) * ASTR + k0 + t];
                uint32_t a1 = as[(m0 + 8 + g) * ASTR + k0 + t];
                uint32_t a2 = as[(m0 + g) * ASTR + k0 + t + 4];
                uint32_t a3 = as[(m0 + 8 + g) * ASTR + k0 + t + 4];
                if (CVT_A) { a0 = f2tf(a0); a1 = f2tf(a1); a2 = f2tf(a2); a3 = f2tf(a3); }
                af[mt][0] = a0; af[mt][1] = a1; af[mt][2] = a2; af[mt][3] = a3;
            }
#pragma unroll
            for (int nt = 0; nt < 4; nt++) {
                int n0 = wn * 32 + nt * 8;
                bf[nt][0] = bs[(k0 + t) * BSTR + n0 + g];
                bf[nt][1] = bs[(k0 + t + 4) * BSTR + n0 + g];
            }
#pragma unroll
            for (int mt = 0; mt < 4; mt++)
#pragma unroll
                for (int nt = 0; nt < 4; nt++) {
                    asm volatile(
                        "mma.sync.aligned.m16n8k8.row.col.f32.tf32.tf32.f32 "
                        "{%0,%1,%2,%3}, {%4,%5,%6,%7}, {%8,%9}, {%0,%1,%2,%3};\n"
                        : "+f"(acc[mt][nt][0]), "+f"(acc[mt][nt][1]),
                          "+f"(acc[mt][nt][2]), "+f"(acc[mt][nt][3])
                        : "r"(af[mt][0]), "r"(af[mt][1]), "r"(af[mt][2]), "r"(af[mt][3]),
                          "r"(bf[nt][0]), "r"(bf[nt][1]));
                }
        }
        __syncthreads();
    }

    // epilogue: + bias, fp16 pack, guarded store
#pragma unroll
    for (int mt = 0; mt < 4; mt++) {
        int r0 = blockRow + wm * 64 + mt * 16 + g;
        int r1 = r0 + 8;
#pragma unroll
        for (int nt = 0; nt < 4; nt++) {
            int col = blockCol + wn * 32 + nt * 8 + 2 * t;
            float bx = __ldg(&bias[col]);
            float by = __ldg(&bias[col + 1]);
            if (r0 < M)
                *(uint32_t*)&C[(size_t)r0 * N + col] = pack_h2(acc[mt][nt][0] + bx, acc[mt][nt][1] + by);
            if (r1 < M)
                *(uint32_t*)&C[(size_t)r1 * N + col] = pack_h2(acc[mt][nt][2] + bx, acc[mt][nt][3] + by);
        }
    }
}

// ---------------------------------------------------------------------------
// SpMM + ReLU, fp16 gather source (L2-only: no L1 reuse exists), fp32
// accumulate, templated output. fp32 output is tf32-rounded at store so the
// consumer GEMM needs no per-fragment cvts.
// One warp per row; full 32-edge batches, unroll 16 for deep MLP.
// ---------------------------------------------------------------------------
template <typename OutT>
__global__ __launch_bounds__(256)
void spmm_relu(const int* __restrict__ rp, const int* __restrict__ cols,
               const float* __restrict__ vals, const __half* __restrict__ S,
               OutT* __restrict__ H) {
    const int warp = threadIdx.x >> 5;
    const int lane = threadIdx.x & 31;
    const int r = blockIdx.x * 8 + warp;
    if (r >= NNODES) return;

    const int start = rp[r];
    const int end   = rp[r + 1];
    const int foff  = lane * 8;

    float acc[8];
#pragma unroll
    for (int i = 0; i < 8; i++) acc[i] = 0.f;

    int base = start;
    // full batches: fixed 32-trip inner loop, deep unroll for MLP
    for (; base + 32 <= end; base += 32) {
        int   cc = __ldg(&cols[base + lane]);
        float vv = __ldg(&vals[base + lane]);
#pragma unroll 16
        for (int j = 0; j < 32; j++) {
            int   col = __shfl_sync(0xffffffffu, cc, j);
            float v   = __shfl_sync(0xffffffffu, vv, j);
            uint4 u = __ldcg((const uint4*)(S + (size_t)col * NHID + foff));
            const __half2* hp = (const __half2*)&u;
            float2 f0 = __half22float2(hp[0]);
            float2 f1 = __half22float2(hp[1]);
            float2 f2 = __half22float2(hp[2]);
            float2 f3 = __half22float2(hp[3]);
            acc[0] = fmaf(v, f0.x, acc[0]);
            acc[1] = fmaf(v, f0.y, acc[1]);
            acc[2] = fmaf(v, f1.x, acc[2]);
            acc[3] = fmaf(v, f1.y, acc[3]);
            acc[4] = fmaf(v, f2.x, acc[4]);
            acc[5] = fmaf(v, f2.y, acc[5]);
            acc[6] = fmaf(v, f3.x, acc[6]);
            acc[7] = fmaf(v, f3.y, acc[7]);
        }
    }
    // tail
    int rem = end - base;
    if (rem > 0) {
        int   cc = 0;
        float vv = 0.f;
        if (lane < rem) {
            cc = __ldg(&cols[base + lane]);
            vv = __ldg(&vals[base + lane]);
        }
        for (int j = 0; j < rem; j++) {
            int   col = __shfl_sync(0xffffffffu, cc, j);
            float v   = __shfl_sync(0xffffffffu, vv, j);
            uint4 u = __ldcg((const uint4*)(S + (size_t)col * NHID + foff));
            const __half2* hp = (const __half2*)&u;
            float2 f0 = __half22float2(hp[0]);
            float2 f1 = __half22float2(hp[1]);
            float2 f2 = __half22float2(hp[2]);
            float2 f3 = __half22float2(hp[3]);
            acc[0] = fmaf(v, f0.x, acc[0]);
            acc[1] = fmaf(v, f0.y, acc[1]);
            acc[2] = fmaf(v, f1.x, acc[2]);
            acc[3] = fmaf(v, f1.y, acc[3]);
            acc[4] = fmaf(v, f2.x, acc[4]);
            acc[5] = fmaf(v, f2.y, acc[5]);
            acc[6] = fmaf(v, f3.x, acc[6]);
            acc[7] = fmaf(v, f3.y, acc[7]);
        }
    }

    if constexpr (sizeof(OutT) == 2) {
        uint4 o;
        uint32_t* op = (uint32_t*)&o;
#pragma unroll
        for (int i = 0; i < 4; i++)
            op[i] = pack_h2(fmaxf(acc[2 * i], 0.f), fmaxf(acc[2 * i + 1], 0.f));
        *(uint4*)((__half*)H + (size_t)r * NHID + foff) = o;
    } else {
        // fp32 path: relu + tf32 rna-round at store (consumer GEMM feeds raw)
        float o[8];
#pragma unroll
        for (int i = 0; i < 8; i++) o[i] = f2tf_f(fmaxf(acc[i], 0.f));
        float4* hp = (float4*)((float*)H + (size_t)r * NHID + foff);
        hp[0] = make_float4(o[0], o[1], o[2], o[3]);
        hp[1] = make_float4(o[4], o[5], o[6], o[7]);
    }
}

// ---------------------------------------------------------------------------
// Fused FC + log_softmax: out[n,c] = logsoftmax(Z[n,:] @ Wfc + bfc)[c]
// Z is fp16. 256 threads/block, 64 nodes/block, 4 threads/node, 10 classes each
// ---------------------------------------------------------------------------
__global__ __launch_bounds__(256)
void fc_logsoftmax_kernel(const __half* __restrict__ Z, const float* __restrict__ W,
                          const float* __restrict__ bias, float* __restrict__ out, int M) {
    __shared__ float Ws[NHID * NCLASS];   // 40 KB
    __shared__ float bs[NCLASS];

    const int tid = threadIdx.x;
    for (int i = tid; i < NHID * NCLASS; i += 256) Ws[i] = __ldg(&W[i]);
    if (tid < NCLASS) bs[tid] = __ldg(&bias[tid]);
    __syncthreads();

    const int n_raw = blockIdx.x * 64 + (tid >> 2);
    const bool valid = (n_raw < M);
    const int n = valid ? n_raw : (M - 1);
    const int q = tid & 3;

    float acc[10];
#pragma unroll
    for (int c = 0; c < 10; c++) acc[c] = bs[q * 10 + c];

    const __half2* zrow = (const __half2*)(Z + (size_t)n * NHID);
#pragma unroll 4
    for (int k2 = 0; k2 < NHID / 2; k2++) {
        float2 zv = __half22float2(__ldg(&zrow[k2]));
        const float* w0 = &Ws[(2 * k2) * NCLASS + q * 10];
        const float* w1 = w0 + NCLASS;
#pragma unroll
        for (int c = 0; c < 10; c++) {
            acc[c] = fmaf(zv.x, w0[c], acc[c]);
            acc[c] = fmaf(zv.y, w1[c], acc[c]);
        }
    }

    float m = acc[0];
#pragma unroll
    for (int c = 1; c < 10; c++) m = fmaxf(m, acc[c]);
    m = fmaxf(m, __shfl_xor_sync(0xffffffffu, m, 1));
    m = fmaxf(m, __shfl_xor_sync(0xffffffffu, m, 2));

    float s = 0.f;
#pragma unroll
    for (int c = 0; c < 10; c++) s += expf(acc[c] - m);
    s += __shfl_xor_sync(0xffffffffu, s, 1);
    s += __shfl_xor_sync(0xffffffffu, s, 2);

    const float lse = m + logf(s);
    if (valid) {
#pragma unroll
        for (int c = 0; c < 10; c++)
            out[(size_t)n * NCLASS + q * 10 + c] = acc[c] - lse;
    }
}

// ---------------------------------------------------------------------------
// launch
// ---------------------------------------------------------------------------
extern "C" void kernel_launch(void* const* d_in, const int* in_sizes, int n_in,
                              void* d_out, int out_size) {
    const float* x         = (const float*)d_in[0];
    const int*   edge_rows = (const int*)  d_in[1];
    const int*   edge_cols = (const int*)  d_in[2];
    const float* edge_vals = (const float*)d_in[3];
    const float* W1        = (const float*)d_in[4];
    const float* b1        = (const float*)d_in[5];
    const float* W2        = (const float*)d_in[6];
    const float* b2        = (const float*)d_in[7];
    const float* Wfc       = (const float*)d_in[8];
    const float* bfc       = (const float*)d_in[9];
    float* out = (float*)d_out;

    __half* bufA;
    __half* bufB;
    float*  bufC;
    float*  w1t;
    float*  w2t;
    int* rowptr;
    cudaGetSymbolAddress((void**)&bufA, g_bufA);
    cudaGetSymbolAddress((void**)&bufB, g_bufB);
    cudaGetSymbolAddress((void**)&bufC, g_bufC);
    cudaGetSymbolAddress((void**)&w1t, g_w1t);
    cudaGetSymbolAddress((void**)&w2t, g_w2t);
    cudaGetSymbolAddress((void**)&rowptr, g_rowptr);

    // 0. pre-round weights to tf32 (rna)
    round_weights_kernel<<<(NFEAT * NHID + 255) / 256, 256>>>(W1, W2, w1t, w2t);

    // 1. CSR row pointers from sorted edge_rows
    build_rowptr_kernel<<<(NNODES + 1 + 255) / 256, 256>>>(edge_rows, NEDGES, rowptr);

    dim3 ggrid(NHID / TBN, (NNODES + TBM - 1) / TBM);

    // 2. S1 = x @ W1 + b1   (tf32 GEMM; A-side cvt in-kernel, B pre-rounded)
    gemm_tf32_async<true><<<ggrid, 256>>>(x, w1t, b1, bufA, NNODES, NHID, NFEAT);

    // 3. h1 = relu(A @ S1)  (fp16 gather, fp32 out tf32-rounded)
    spmm_relu<float><<<(NNODES + 7) / 8, 256>>>(rowptr, edge_cols, edge_vals, bufA, bufC);

    // 4. S2 = h1 @ W2 + b2  (tf32 GEMM, fully cvt-free)
    gemm_tf32_async<false><<<ggrid, 256>>>(bufC, w2t, b2, bufA, NNODES, NHID, NHID);

    // 5. z = relu(A @ S2)   (fp16 gather, fp16 out)
    spmm_relu<__half><<<(NNODES + 7) / 8, 256>>>(rowptr, edge_cols, edge_vals, bufA, bufB);

    // 6. out = log_softmax(z @ Wfc + bfc)
    fc_logsoftmax_kernel<<<(NNODES + 63) / 64, 256>>>(bufB, Wfc, bfc, out, NNODES);
}

// round 12
// speedup vs baseline: 2.8554x; 1.1612x over previous
#include <cuda_runtime.h>
#include <cuda_fp16.h>
#include <math.h>
#include <stdint.h>

// Problem constants (fixed by the reference)
#define NNODES 50000
#define NEDGES 1600000
#define NFEAT  512
#define NHID   256
#define NCLASS 40
#define NCPAD  128   // Wfc padded column count (one GEMM tile)

// Scratch (allocation-free rule: __device__ globals).
__device__ __align__(16) __half g_bufA[NNODES * NHID];   // 25.6 MB (S1, S2; then reused as fp32 [N,128] fc output)
__device__ __align__(16) float  g_bufC[NNODES * NHID];   // 51.2 MB (h1, then z; fp32 tf32-rounded)
__device__ __align__(16) float  g_w1t[NFEAT * NHID];     // W1 tf32-rounded
__device__ __align__(16) float  g_w2t[NHID * NHID];      // W2 tf32-rounded
__device__ __align__(16) float  g_wfct[NHID * NCPAD];    // Wfc tf32-rounded, zero-padded to 128 cols
__device__ __align__(16) float  g_bfcp[NCPAD];           // bfc zero-padded
__device__ int g_rowptr[NNODES + 1];

__device__ __forceinline__ uint32_t pack_h2(float lo, float hi) {
    __half2 h = __floats2half2_rn(lo, hi);
    return *(uint32_t*)&h;
}

// unbiased tf32 rounding (round-to-nearest) — REQUIRED: RZ truncation is biased
// and blows up the K-long reductions (measured: rel_err 1.0e-3 vs 1.6e-4).
// mma.tf32 truncation is the IDENTITY on pre-rounded values.
__device__ __forceinline__ uint32_t f2tf(uint32_t raw) {
    uint32_t u;
    asm("cvt.rna.tf32.f32 %0, %1;" : "=r"(u) : "r"(raw));
    return u;
}
__device__ __forceinline__ float f2tf_f(float x) {
    return __uint_as_float(f2tf(__float_as_uint(x)));
}

__device__ __forceinline__ void cp_async16(uint32_t dst, const void* src, int src_bytes) {
    asm volatile("cp.async.cg.shared.global [%0], [%1], 16, %2;\n"
                 :: "r"(dst), "l"(src), "r"(src_bytes));
}
__device__ __forceinline__ void cp_commit() {
    asm volatile("cp.async.commit_group;\n" ::: "memory");
}
__device__ __forceinline__ void cp_wait1() {
    asm volatile("cp.async.wait_group 1;\n" ::: "memory");
}

// ---------------------------------------------------------------------------
// Pre-round weights to tf32 (rna) + build padded Wfc/bfc.
// ---------------------------------------------------------------------------
__global__ void prep_weights_kernel(const float* __restrict__ W1, const float* __restrict__ W2,
                                    const float* __restrict__ Wfc, const float* __restrict__ bfc,
                                    float* __restrict__ w1t, float* __restrict__ w2t,
                                    float* __restrict__ wfct, float* __restrict__ bfcp) {
    int i = blockIdx.x * blockDim.x + threadIdx.x;
    if (i < NFEAT * NHID) w1t[i] = f2tf_f(__ldg(&W1[i]));
    if (i < NHID * NHID)  w2t[i] = f2tf_f(__ldg(&W2[i]));
    if (i < NHID * NCPAD) {
        int k = i / NCPAD, c = i % NCPAD;
        wfct[i] = (c < NCLASS) ? f2tf_f(__ldg(&Wfc[k * NCLASS + c])) : 0.f;
    }
    if (i < NCPAD) bfcp[i] = (i < NCLASS) ? __ldg(&bfc[i]) : 0.f;
}

// ---------------------------------------------------------------------------
// row_ptr build: edge_rows is sorted -> lower_bound per row
// ---------------------------------------------------------------------------
__global__ void build_rowptr_kernel(const int* __restrict__ rows, int E, int* __restrict__ rp) {
    int r = blockIdx.x * blockDim.x + threadIdx.x;
    if (r > NNODES) return;
    int lo = 0, hi = E;
    while (lo < hi) {
        int mid = (lo + hi) >> 1;
        if (__ldg(&rows[mid]) < r) lo = mid + 1; else hi = mid;
    }
    rp[r] = lo;
}

// ---------------------------------------------------------------------------
// Unified TF32 GEMM + bias, cp.async double-buffered, 2 CTA/SM.
// C[M,N] = A[M,K] @ B[K,N] + bias.  B is ALWAYS pre-rounded tf32 (raw feed).
// A rna-rounded in registers iff CVT_A; else pre-rounded by producer.
// OutT = __half (pack) or float (raw store).
// ---------------------------------------------------------------------------
#define TBM 128
#define TBN 128
#define TBK 16
#define ASTR 20
#define BSTR 136

template <bool CVT_A, typename OutT>
__global__ __launch_bounds__(256, 2)
void gemm_tf32_async(const float* __restrict__ A, const float* __restrict__ B,
                     const float* __restrict__ bias, OutT* __restrict__ C,
                     int M, int N, int K) {
    __shared__ float As[2][TBM * ASTR];
    __shared__ float Bs[2][TBK * BSTR];

    const int tid  = threadIdx.x;
    const int warp = tid >> 5;
    const int lane = tid & 31;
    const int g = lane >> 2;
    const int t = lane & 3;
    const int wm = warp & 1;
    const int wn = warp >> 1;

    const int blockRow = blockIdx.y * TBM;
    const int blockCol = blockIdx.x * TBN;
    const int ntiles = K / TBK;

    uint32_t as_base = (uint32_t)__cvta_generic_to_shared(&As[0][0]);
    uint32_t bs_base = (uint32_t)__cvta_generic_to_shared(&Bs[0][0]);
    const uint32_t as_sz = TBM * ASTR * 4;
    const uint32_t bs_sz = TBK * BSTR * 4;

    auto load_tile = [&](int kt, int b) {
        int k0 = kt * TBK;
#pragma unroll
        for (int j = 0; j < 2; j++) {
            int c   = tid + j * 256;
            int row = c >> 2;
            int f   = (c & 3) * 4;
            int grow = blockRow + row;
            int ok = (grow < M) ? 16 : 0;
            int gr = (grow < M) ? grow : (M - 1);
            cp_async16(as_base + b * as_sz + (row * ASTR + f) * 4,
                       A + (size_t)gr * K + k0 + f, ok);
        }
#pragma unroll
        for (int j = 0; j < 2; j++) {
            int c   = tid + j * 256;
            int row = c >> 5;
            int f   = (c & 31) * 4;
            cp_async16(bs_base + b * bs_sz + (row * BSTR + f) * 4,
                       B + (size_t)(k0 + row) * N + blockCol + f, 16);
        }
    };

    float acc[4][4][4];
#pragma unroll
    for (int mt = 0; mt < 4; mt++)
#pragma unroll
        for (int nt = 0; nt < 4; nt++)
#pragma unroll
            for (int q = 0; q < 4; q++) acc[mt][nt][q] = 0.f;

    load_tile(0, 0);
    cp_commit();

    for (int kt = 0; kt < ntiles; kt++) {
        if (kt + 1 < ntiles) load_tile(kt + 1, (kt + 1) & 1);
        cp_commit();
        cp_wait1();
        __syncthreads();

        const uint32_t* as = (const uint32_t*)As[kt & 1];
        const uint32_t* bs = (const uint32_t*)Bs[kt & 1];

#pragma unroll
        for (int ks = 0; ks < 2; ks++) {
            const int k0 = ks * 8;
            uint32_t af[4][4];
            uint32_t bf[4][2];
#pragma unroll
            for (int mt = 0; mt < 4; mt++) {
                int m0 = wm * 64 + mt * 16;
                uint32_t a0 = as[(m0 + g) * ASTR + k0 + t];
                uint32_t a1 = as[(m0 + 8 + g) * ASTR + k0 + t];
                uint32_t a2 = as[(m0 + g) * ASTR + k0 + t + 4];
                uint32_t a3 = as[(m0 + 8 + g) * ASTR + k0 + t + 4];
                if (CVT_A) { a0 = f2tf(a0); a1 = f2tf(a1); a2 = f2tf(a2); a3 = f2tf(a3); }
                af[mt][0] = a0; af[mt][1] = a1; af[mt][2] = a2; af[mt][3] = a3;
            }
#pragma unroll
            for (int nt = 0; nt < 4; nt++) {
                int n0 = wn * 32 + nt * 8;
                bf[nt][0] = bs[(k0 + t) * BSTR + n0 + g];
                bf[nt][1] = bs[(k0 + t + 4) * BSTR + n0 + g];
            }
#pragma unroll
            for (int mt = 0; mt < 4; mt++)
#pragma unroll
                for (int nt = 0; nt < 4; nt++) {
                    asm volatile(
                        "mma.sync.aligned.m16n8k8.row.col.f32.tf32.tf32.f32 "
                        "{%0,%1,%2,%3}, {%4,%5,%6,%7}, {%8,%9}, {%0,%1,%2,%3};\n"
                        : "+f"(acc[mt][nt][0]), "+f"(acc[mt][nt][1]),
                          "+f"(acc[mt][nt][2]), "+f"(acc[mt][nt][3])
                        : "r"(af[mt][0]), "r"(af[mt][1]), "r"(af[mt][2]), "r"(af[mt][3]),
                          "r"(bf[nt][0]), "r"(bf[nt][1]));
                }
        }
        __syncthreads();
    }

    // epilogue: + bias, guarded store (fp16 pack or fp32 raw)
#pragma unroll
    for (int mt = 0; mt < 4; mt++) {
        int r0 = blockRow + wm * 64 + mt * 16 + g;
        int r1 = r0 + 8;
#pragma unroll
        for (int nt = 0; nt < 4; nt++) {
            int col = blockCol + wn * 32 + nt * 8 + 2 * t;
            float bx = __ldg(&bias[col]);
            float by = __ldg(&bias[col + 1]);
            if constexpr (sizeof(OutT) == 2) {
                if (r0 < M)
                    *(uint32_t*)&((__half*)C)[(size_t)r0 * N + col] = pack_h2(acc[mt][nt][0] + bx, acc[mt][nt][1] + by);
                if (r1 < M)
                    *(uint32_t*)&((__half*)C)[(size_t)r1 * N + col] = pack_h2(acc[mt][nt][2] + bx, acc[mt][nt][3] + by);
            } else {
                if (r0 < M)
                    *(float2*)&((float*)C)[(size_t)r0 * N + col] = make_float2(acc[mt][nt][0] + bx, acc[mt][nt][1] + by);
                if (r1 < M)
                    *(float2*)&((float*)C)[(size_t)r1 * N + col] = make_float2(acc[mt][nt][2] + bx, acc[mt][nt][3] + by);
            }
        }
    }
}

// ---------------------------------------------------------------------------
// SpMM + ReLU, fp16 gather source (L2-resident, __ldcg), fp32 accumulate,
// fp32 output tf32-rounded at store (consumers are cvt-free tf32 GEMMs).
// One warp per row; full 32-edge batches, unroll 16.
// ---------------------------------------------------------------------------
__global__ __launch_bounds__(256)
void spmm_relu(const int* __restrict__ rp, const int* __restrict__ cols,
               const float* __restrict__ vals, const __half* __restrict__ S,
               float* __restrict__ H) {
    const int warp = threadIdx.x >> 5;
    const int lane = threadIdx.x & 31;
    const int r = blockIdx.x * 8 + warp;
    if (r >= NNODES) return;

    const int start = rp[r];
    const int end   = rp[r + 1];
    const int foff  = lane * 8;

    float acc[8];
#pragma unroll
    for (int i = 0; i < 8; i++) acc[i] = 0.f;

    int base = start;
    for (; base + 32 <= end; base += 32) {
        int   cc = __ldg(&cols[base + lane]);
        float vv = __ldg(&vals[base + lane]);
#pragma unroll 16
        for (int j = 0; j < 32; j++) {
            int   col = __shfl_sync(0xffffffffu, cc, j);
            float v   = __shfl_sync(0xffffffffu, vv, j);
            uint4 u = __ldcg((const uint4*)(S + (size_t)col * NHID + foff));
            const __half2* hp = (const __half2*)&u;
            float2 f0 = __half22float2(hp[0]);
            float2 f1 = __half22float2(hp[1]);
            float2 f2 = __half22float2(hp[2]);
            float2 f3 = __half22float2(hp[3]);
            acc[0] = fmaf(v, f0.x, acc[0]);
            acc[1] = fmaf(v, f0.y, acc[1]);
            acc[2] = fmaf(v, f1.x, acc[2]);
            acc[3] = fmaf(v, f1.y, acc[3]);
            acc[4] = fmaf(v, f2.x, acc[4]);
            acc[5] = fmaf(v, f2.y, acc[5]);
            acc[6] = fmaf(v, f3.x, acc[6]);
            acc[7] = fmaf(v, f3.y, acc[7]);
        }
    }
    int rem = end - base;
    if (rem > 0) {
        int   cc = 0;
        float vv = 0.f;
        if (lane < rem) {
            cc = __ldg(&cols[base + lane]);
            vv = __ldg(&vals[base + lane]);
        }
        for (int j = 0; j < rem; j++) {
            int   col = __shfl_sync(0xffffffffu, cc, j);
            float v   = __shfl_sync(0xffffffffu, vv, j);
            uint4 u = __ldcg((const uint4*)(S + (size_t)col * NHID + foff));
            const __half2* hp = (const __half2*)&u;
            float2 f0 = __half22float2(hp[0]);
            float2 f1 = __half22float2(hp[1]);
            float2 f2 = __half22float2(hp[2]);
            float2 f3 = __half22float2(hp[3]);
            acc[0] = fmaf(v, f0.x, acc[0]);
            acc[1] = fmaf(v, f0.y, acc[1]);
            acc[2] = fmaf(v, f1.x, acc[2]);
            acc[3] = fmaf(v, f1.y, acc[3]);
            acc[4] = fmaf(v, f2.x, acc[4]);
            acc[5] = fmaf(v, f2.y, acc[5]);
            acc[6] = fmaf(v, f3.x, acc[6]);
            acc[7] = fmaf(v, f3.y, acc[7]);
        }
    }

    // relu + tf32 rna-round at store (consumer GEMM feeds raw)
    float o[8];
#pragma unroll
    for (int i = 0; i < 8; i++) o[i] = f2tf_f(fmaxf(acc[i], 0.f));
    float4* hp = (float4*)(H + (size_t)r * NHID + foff);
    hp[0] = make_float4(o[0], o[1], o[2], o[3]);
    hp[1] = make_float4(o[4], o[5], o[6], o[7]);
}

// ---------------------------------------------------------------------------
// log_softmax over the first NCLASS cols of ZF[M, NCPAD]:
// out[n,c] = zf[n,c] - logsumexp(zf[n,0:40]).
// 8 lanes per node, 5 classes per lane; 32 nodes per 256-thread block.
// ---------------------------------------------------------------------------
__global__ __launch_bounds__(256)
void logsoftmax_kernel(const float* __restrict__ ZF, float* __restrict__ out, int M) {
    const int lane = threadIdx.x & 31;
    const int warp = threadIdx.x >> 5;
    const int sub  = lane & 7;              // 0..7 (class group)
    const int nw   = lane >> 3;             // 0..3 (node within warp)
    const int n_raw = blockIdx.x * 32 + warp * 4 + nw;
    const bool valid = (n_raw < M);
    const int n = valid ? n_raw : (M - 1);

    float v[5];
#pragma unroll
    for (int i = 0; i < 5; i++)
        v[i] = __ldg(&ZF[(size_t)n * NCPAD + sub * 5 + i]);

    float m = v[0];
#pragma unroll
    for (int i = 1; i < 5; i++) m = fmaxf(m, v[i]);
    m = fmaxf(m, __shfl_xor_sync(0xffffffffu, m, 1));
    m = fmaxf(m, __shfl_xor_sync(0xffffffffu, m, 2));
    m = fmaxf(m, __shfl_xor_sync(0xffffffffu, m, 4));

    float s = 0.f;
#pragma unroll
    for (int i = 0; i < 5; i++) s += expf(v[i] - m);
    s += __shfl_xor_sync(0xffffffffu, s, 1);
    s += __shfl_xor_sync(0xffffffffu, s, 2);
    s += __shfl_xor_sync(0xffffffffu, s, 4);

    const float lse = m + logf(s);
    if (valid) {
#pragma unroll
        for (int i = 0; i < 5; i++)
            out[(size_t)n * NCLASS + sub * 5 + i] = v[i] - lse;
    }
}

// ---------------------------------------------------------------------------
// launch
// ---------------------------------------------------------------------------
extern "C" void kernel_launch(void* const* d_in, const int* in_sizes, int n_in,
                              void* d_out, int out_size) {
    const float* x         = (const float*)d_in[0];
    const int*   edge_rows = (const int*)  d_in[1];
    const int*   edge_cols = (const int*)  d_in[2];
    const float* edge_vals = (const float*)d_in[3];
    const float* W1        = (const float*)d_in[4];
    const float* b1        = (const float*)d_in[5];
    const float* W2        = (const float*)d_in[6];
    const float* b2        = (const float*)d_in[7];
    const float* Wfc       = (const float*)d_in[8];
    const float* bfc       = (const float*)d_in[9];
    float* out = (float*)d_out;

    __half* bufA;
    float*  bufC;
    float*  w1t;
    float*  w2t;
    float*  wfct;
    float*  bfcp;
    int* rowptr;
    cudaGetSymbolAddress((void**)&bufA, g_bufA);
    cudaGetSymbolAddress((void**)&bufC, g_bufC);
    cudaGetSymbolAddress((void**)&w1t, g_w1t);
    cudaGetSymbolAddress((void**)&w2t, g_w2t);
    cudaGetSymbolAddress((void**)&wfct, g_wfct);
    cudaGetSymbolAddress((void**)&bfcp, g_bfcp);
    cudaGetSymbolAddress((void**)&rowptr, g_rowptr);

    // 0. pre-round weights to tf32; pad Wfc to [256,128]
    prep_weights_kernel<<<(NFEAT * NHID + 255) / 256, 256>>>(W1, W2, Wfc, bfc,
                                                             w1t, w2t, wfct, bfcp);

    // 1. CSR row pointers from sorted edge_rows
    build_rowptr_kernel<<<(NNODES + 1 + 255) / 256, 256>>>(edge_rows, NEDGES, rowptr);

    dim3 ggrid(NHID / TBN, (NNODES + TBM - 1) / TBM);

    // 2. S1 = x @ W1 + b1   (tf32 GEMM; A-side cvt in-kernel, fp16 out)
    gemm_tf32_async<true, __half><<<ggrid, 256>>>(x, w1t, b1, bufA, NNODES, NHID, NFEAT);

    // 3. h1 = relu(A @ S1)  (fp16 gather -> fp32 tf32-rounded)
    spmm_relu<<<(NNODES + 7) / 8, 256>>>(rowptr, edge_cols, edge_vals, bufA, bufC);

    // 4. S2 = h1 @ W2 + b2  (cvt-free tf32 GEMM, fp16 out)
    gemm_tf32_async<false, __half><<<ggrid, 256>>>(bufC, w2t, b2, bufA, NNODES, NHID, NHID);

    // 5. z = relu(A @ S2)   (fp16 gather -> fp32 tf32-rounded; overwrites h1)
    spmm_relu<<<(NNODES + 7) / 8, 256>>>(rowptr, edge_cols, edge_vals, bufA, bufC);

    // 6. ZF = z @ WfcPad + bfcPad  (cvt-free tf32 GEMM, fp32 out into bufA storage)
    float* zf = (float*)bufA;   // 25.6 MB = 50000 x 128 fp32
    {
        dim3 fcgrid(1, (NNODES + TBM - 1) / TBM);
        gemm_tf32_async<false, float><<<fcgrid, 256>>>(bufC, wfct, bfcp, zf, NNODES, NCPAD, NHID);
    }

    // 7. out = log_softmax(ZF[:, 0:40])
    logsoftmax_kernel<<<(NNODES + 31) / 32, 256>>>(zf, out, NNODES);
}